// round 11
// baseline (speedup 1.0000x reference)
#include <cuda_runtime.h>
#include <cuda_fp16.h>
#include <cstdint>

// ---------------------------------------------------------------------------
// Upsampling_77214922047593 — legacy mma.sync fp16 single-pass (sm_103 base).
//   fused12:  h2 = unary(unary(support @ W1) @ W2)   65536 rows (h1 in smem)
//   layer3:   out = unary((gather(h2)+query) @ W3)   262144 rows
// R10->R11: layer3 is PERSISTENT (grid=152, 1 wave): W3 (4 chunks, 147.5KB)
// loaded into smem once per CTA, stride loop over 2048 row-blocks.
// Removes 13.8 waves of prologue/epilogue, all steady-state cp.async B
// restreaming, and the s_grow smem round-trip.
// ---------------------------------------------------------------------------

namespace {
constexpr int Mm   = 16384;
constexpr int CIN  = 512;
constexpr int COUT = 256;
constexpr float EPSv   = 1e-5f;
constexpr float SLOPEv = 0.1f;

constexpr int ROWS12 = 65536;
constexpr int ROWS3  = 262144;

constexpr int TILE_M = 128;
constexpr int KC     = 64;         // K per smem chunk
constexpr int ASTRE  = 72;         // padded row stride in fp16 elems (144B)

constexpr int A_BYTES   = TILE_M * ASTRE * 2;   // 18432
constexpr int B_BYTES   = COUT   * ASTRE * 2;   // 36864
// fused kernel: A1 double buf + B double buf + A2 (4 chunks, h1 tile)
constexpr size_t SMEM_F = 2 * (size_t)A_BYTES + 2 * B_BYTES + 4 * A_BYTES; // 184320
// layer-3 persistent: A double buf + B resident (4 chunks)
constexpr size_t SMEM_3 = 2 * (size_t)A_BYTES + 4 * B_BYTES;               // 184320

constexpr int NBLK3 = ROWS3 / TILE_M;   // 2048
constexpr int GRID3 = 152;              // 1 wave on GB300
} // namespace

__device__ __half g_h2f[(size_t)ROWS12 * COUT];     // fp16 h2 (32 MB)
// pre-rounded, pre-transposed weights: Wt[layer][n][k], fp16
__device__ __half g_Wth[3][COUT][CIN];

// ---------------- helpers ----------------
__device__ __forceinline__ uint32_t smem_u32(const void* p) {
    uint32_t a;
    asm("{ .reg .u64 t; cvta.to.shared.u64 t, %1; cvt.u32.u64 %0, t; }"
        : "=r"(a) : "l"(p));
    return a;
}

#define LDSM4(r, addr)                                                         \
    asm volatile("ldmatrix.sync.aligned.m8n8.x4.shared.b16 {%0,%1,%2,%3}, [%4];" \
        : "=r"((r)[0]), "=r"((r)[1]), "=r"((r)[2]), "=r"((r)[3]) : "r"(addr))

#define MMA_F16(c, a, b0, b1)                                                  \
    asm volatile("mma.sync.aligned.m16n8k16.row.col.f32.f16.f16.f32 "          \
        "{%0,%1,%2,%3}, {%4,%5,%6,%7}, {%8,%9}, {%0,%1,%2,%3};"                \
        : "+f"((c)[0]), "+f"((c)[1]), "+f"((c)[2]), "+f"((c)[3])               \
        : "r"((a)[0]), "r"((a)[1]), "r"((a)[2]), "r"((a)[3]),                  \
          "r"(b0), "r"(b1))

#define CP_ASYNC8(dst, src)                                                    \
    asm volatile("cp.async.ca.shared.global [%0], [%1], 8;"                    \
        :: "r"(dst), "l"(src))
#define CP_COMMIT() asm volatile("cp.async.commit_group;" ::: "memory")
#define CP_WAIT0()  asm volatile("cp.async.wait_group 0;" ::: "memory")

__device__ __forceinline__ void round4h(float4 v, uint32_t h[2]) {
    __half2 h01 = __floats2half2_rn(v.x, v.y);
    __half2 h23 = __floats2half2_rn(v.z, v.w);
    h[0] = *reinterpret_cast<uint32_t*>(&h01);
    h[1] = *reinterpret_cast<uint32_t*>(&h23);
}

// GroupNorm-of-8 + affine + leaky-relu on one n8 tile's 4 acc values.
__device__ __forceinline__ void gn8(float v0, float v1, float v2, float v3,
                                    float2 gg, float2 be,
                                    float& y0, float& y1, float& y2, float& y3)
{
    float s0 = v0 + v1,           s1 = v2 + v3;
    float t0 = v0 * v0 + v1 * v1, t1 = v2 * v2 + v3 * v3;
    s0 += __shfl_xor_sync(0xffffffffu, s0, 1);
    s0 += __shfl_xor_sync(0xffffffffu, s0, 2);
    s1 += __shfl_xor_sync(0xffffffffu, s1, 1);
    s1 += __shfl_xor_sync(0xffffffffu, s1, 2);
    t0 += __shfl_xor_sync(0xffffffffu, t0, 1);
    t0 += __shfl_xor_sync(0xffffffffu, t0, 2);
    t1 += __shfl_xor_sync(0xffffffffu, t1, 1);
    t1 += __shfl_xor_sync(0xffffffffu, t1, 2);
    const float m0 = s0 * 0.125f, m1 = s1 * 0.125f;
    const float r0 = rsqrtf(fmaxf(t0 * 0.125f - m0 * m0, 0.f) + EPSv);
    const float r1 = rsqrtf(fmaxf(t1 * 0.125f - m1 * m1, 0.f) + EPSv);
    y0 = (v0 - m0) * r0 * gg.x + be.x;
    y1 = (v1 - m0) * r0 * gg.y + be.y;
    y2 = (v2 - m1) * r1 * gg.x + be.x;
    y3 = (v3 - m1) * r1 * gg.y + be.y;
    y0 = (y0 >= 0.f) ? y0 : SLOPEv * y0;
    y1 = (y1 >= 0.f) ? y1 : SLOPEv * y1;
    y2 = (y2 >= 0.f) ? y2 : SLOPEv * y2;
    y3 = (y3 >= 0.f) ? y3 : SLOPEv * y3;
}

// ---------------- weight prologue: round + transpose ----------------
__global__ void split_w_kernel(const float* __restrict__ W, int layer) {
    int k = blockIdx.x;
    int n = threadIdx.x;
    g_Wth[layer][n][k] = __float2half_rn(W[(size_t)k * COUT + n]);
}

// ---------------- fused layers 1+2 (unchanged from R10) ----------------
__global__ void __launch_bounds__(512, 1)
fused12_kernel(const float* __restrict__ support,
               const float* __restrict__ b1, const float* __restrict__ g1,
               const float* __restrict__ be1,
               const float* __restrict__ b2, const float* __restrict__ g2,
               const float* __restrict__ be2)
{
    constexpr int NC1 = CIN / KC;    // 8
    constexpr int NC2 = COUT / KC;   // 4

    extern __shared__ __align__(16) char smc[];
    const uint32_t sbase  = smem_u32(smc);
    const uint32_t bBase  = sbase + 2 * A_BYTES;
    const uint32_t a2Base = bBase + 2 * B_BYTES;
    char* a2c = smc + 2 * A_BYTES + 2 * B_BYTES;

    const int tid  = threadIdx.x;
    const int wid  = tid >> 5;
    const int lane = tid & 31;
    const int rowBlk = blockIdx.x * TILE_M;

    const __half* W1h = &g_Wth[0][0][0];
    const __half* W2h = &g_Wth[1][0][0];

    float4 vpipe[4];
    auto ldgA1 = [&](int kc) {
#pragma unroll
        for (int i = 0; i < 4; i++) {
            int s  = tid + i * 512;
            int r  = s >> 4;
            int c4 = (s & 15) * 4;
            vpipe[i] = *(const float4*)(support + (size_t)(rowBlk + r) * CIN + kc + c4);
        }
    };
    auto stsA1 = [&](int buf) {
        char* ab = smc + buf * A_BYTES;
#pragma unroll
        for (int i = 0; i < 4; i++) {
            int s  = tid + i * 512;
            int r  = s >> 4;
            int c4 = (s & 15) * 4;
            uint32_t h[2];
            round4h(vpipe[i], h);
            *(uint2*)(ab + (r * ASTRE + c4) * 2) = make_uint2(h[0], h[1]);
        }
    };
    auto cpB = [&](const __half* Wsrc, int kc, int buf) {
        uint32_t bh = bBase + buf * B_BYTES;
#pragma unroll
        for (int i = 0; i < 8; i++) {
            int q   = tid + i * 512;
            int n   = q >> 4;
            int seg = q & 15;
            CP_ASYNC8(bh + (uint32_t)(n * ASTRE + seg * 4) * 2,
                      Wsrc + (size_t)n * CIN + kc + seg * 4);
        }
    };

    const int wm = wid & 3;
    const int wn = wid >> 2;
    const int wr = wm * 32;
    const int wc = wn * 64;
    const int qlane = lane & 3;

    float acc[2][8][4];
#pragma unroll
    for (int mi = 0; mi < 2; mi++)
#pragma unroll
        for (int j = 0; j < 8; j++)
#pragma unroll
            for (int c = 0; c < 4; c++) acc[mi][j][c] = 0.f;

    const int a_r  = (lane & 15);
    const int a_kh = (lane >> 4) * 8;
    const int b_r  = ((lane >> 4) & 1) * 8 + (lane & 7);
    const int b_kh = ((lane >> 3) & 1) * 8;

    // ================= GEMM 1 (K=512) =================
    ldgA1(0);
    cpB(W1h, 0, 0);
    CP_COMMIT();
    stsA1(0);

#pragma unroll 1
    for (int c = 0; c < NC1; c++) {
        const int cb = c & 1;
        const bool more = (c + 1 < NC1);
        if (more) ldgA1((c + 1) * KC);
        CP_WAIT0();
        __syncthreads();
        if (more) { cpB(W1h, (c + 1) * KC, (c + 1) & 1); CP_COMMIT(); }

        const uint32_t aH = sbase + cb * A_BYTES;
        const uint32_t bH = bBase + cb * B_BYTES;
#pragma unroll
        for (int ks = 0; ks < 4; ks++) {
            const int k0 = ks * 16;
            uint32_t ah[2][4];
#pragma unroll
            for (int mi = 0; mi < 2; mi++)
                LDSM4(ah[mi], aH + (uint32_t)((wr + mi * 16 + a_r) * ASTRE + k0 + a_kh) * 2);
#pragma unroll
            for (int jp = 0; jp < 4; jp++) {
                uint32_t bhr[4];
                LDSM4(bhr, bH + (uint32_t)((wc + jp * 16 + b_r) * ASTRE + k0 + b_kh) * 2);
#pragma unroll
                for (int mi = 0; mi < 2; mi++)
#pragma unroll
                    for (int jj = 0; jj < 2; jj++)
                        MMA_F16(acc[mi][jp * 2 + jj], ah[mi],
                                bhr[jj * 2], bhr[jj * 2 + 1]);
            }
        }
        if (more) stsA1((c + 1) & 1);
    }

    cpB(W2h, 0, 0);
    CP_COMMIT();

    // ---- epilogue 1: GN -> fp16 h1 tile into A2 smem ----
#pragma unroll
    for (int j = 0; j < 8; j++) {
        const int col = wc + j * 8 + 2 * qlane;
        const int kk  = j * 8 + 2 * qlane;
        const float2 bb = *reinterpret_cast<const float2*>(b1 + col);
        const float2 gg = *reinterpret_cast<const float2*>(g1 + col);
        const float2 be = *reinterpret_cast<const float2*>(be1 + col);
#pragma unroll
        for (int mi = 0; mi < 2; mi++) {
            float y0, y1, y2, y3;
            gn8(acc[mi][j][0] + bb.x, acc[mi][j][1] + bb.y,
                acc[mi][j][2] + bb.x, acc[mi][j][3] + bb.y, gg, be,
                y0, y1, y2, y3);
            const int row0 = wr + mi * 16 + (lane >> 2);
            *(__half2*)(a2c + wn * A_BYTES + (row0 * ASTRE + kk) * 2)       = __floats2half2_rn(y0, y1);
            *(__half2*)(a2c + wn * A_BYTES + ((row0 + 8) * ASTRE + kk) * 2) = __floats2half2_rn(y2, y3);
        }
    }

#pragma unroll
    for (int mi = 0; mi < 2; mi++)
#pragma unroll
        for (int j = 0; j < 8; j++)
#pragma unroll
            for (int c = 0; c < 4; c++) acc[mi][j][c] = 0.f;

    __syncthreads();

    // ================= GEMM 2 (K=256, A resident in smem) =================
#pragma unroll 1
    for (int c = 0; c < NC2; c++) {
        const int cb = c & 1;
        const bool more = (c + 1 < NC2);
        CP_WAIT0();
        __syncthreads();
        if (more) { cpB(W2h, (c + 1) * KC, (c + 1) & 1); CP_COMMIT(); }

        const uint32_t aH = a2Base + c * A_BYTES;
        const uint32_t bH = bBase + cb * B_BYTES;
#pragma unroll
        for (int ks = 0; ks < 4; ks++) {
            const int k0 = ks * 16;
            uint32_t ah[2][4];
#pragma unroll
            for (int mi = 0; mi < 2; mi++)
                LDSM4(ah[mi], aH + (uint32_t)((wr + mi * 16 + a_r) * ASTRE + k0 + a_kh) * 2);
#pragma unroll
            for (int jp = 0; jp < 4; jp++) {
                uint32_t bhr[4];
                LDSM4(bhr, bH + (uint32_t)((wc + jp * 16 + b_r) * ASTRE + k0 + b_kh) * 2);
#pragma unroll
                for (int mi = 0; mi < 2; mi++)
#pragma unroll
                    for (int jj = 0; jj < 2; jj++)
                        MMA_F16(acc[mi][jp * 2 + jj], ah[mi],
                                bhr[jj * 2], bhr[jj * 2 + 1]);
            }
        }
    }

    // ---- epilogue 2: GN -> fp16 h2 to global ----
#pragma unroll
    for (int j = 0; j < 8; j++) {
        const int col = wc + j * 8 + 2 * qlane;
        const float2 bb = *reinterpret_cast<const float2*>(b2 + col);
        const float2 gg = *reinterpret_cast<const float2*>(g2 + col);
        const float2 be = *reinterpret_cast<const float2*>(be2 + col);
#pragma unroll
        for (int mi = 0; mi < 2; mi++) {
            float y0, y1, y2, y3;
            gn8(acc[mi][j][0] + bb.x, acc[mi][j][1] + bb.y,
                acc[mi][j][2] + bb.x, acc[mi][j][3] + bb.y, gg, be,
                y0, y1, y2, y3);
            const size_t row = (size_t)rowBlk + wr + mi * 16 + (lane >> 2);
            *(__half2*)(g_h2f + row * COUT + col)       = __floats2half2_rn(y0, y1);
            *(__half2*)(g_h2f + (row + 8) * COUT + col) = __floats2half2_rn(y2, y3);
        }
    }
}

// ---------------- layer 3 (persistent, W3 resident in smem) ----------------
__global__ void __launch_bounds__(512, 1)
layer3_kernel(const float* __restrict__ query,
              const float* __restrict__ b3, const float* __restrict__ g3,
              const float* __restrict__ be3,
              const int*   __restrict__ idx,
              float*       __restrict__ out)
{
    constexpr int NC = COUT / KC;   // 4

    extern __shared__ __align__(16) char smc[];
    const uint32_t sbase = smem_u32(smc);
    const uint32_t bBase = sbase + 2 * A_BYTES;

    const int tid  = threadIdx.x;
    const int wid  = tid >> 5;
    const int lane = tid & 31;

    const __half* W3h = &g_Wth[2][0][0];

    // ---- preload ALL of W3 into smem (once per CTA lifetime) ----
#pragma unroll
    for (int ch = 0; ch < NC; ch++) {
        uint32_t bh = bBase + ch * B_BYTES;
#pragma unroll
        for (int i = 0; i < 8; i++) {
            int q   = tid + i * 512;
            int n   = q >> 4;
            int seg = q & 15;
            CP_ASYNC8(bh + (uint32_t)(n * ASTRE + seg * 4) * 2,
                      W3h + (size_t)n * CIN + ch * KC + seg * 4);
        }
    }
    CP_COMMIT();
    CP_WAIT0();
    __syncthreads();

    const int wm = wid & 3;
    const int wn = wid >> 2;
    const int wr = wm * 32;
    const int wc = wn * 64;
    const int qlane = lane & 3;

    const int a_r  = (lane & 15);
    const int a_kh = (lane >> 4) * 8;
    const int b_r  = ((lane >> 4) & 1) * 8 + (lane & 7);
    const int b_kh = ((lane >> 3) & 1) * 8;

    float4 vpipe[4];
    int    gidx[4];

    // ---- persistent loop over row blocks ----
#pragma unroll 1
    for (int blk = blockIdx.x; blk < NBLK3; blk += GRID3) {
        const int rowBlk = blk * TILE_M;

        // per-thread gather row ids (rows fixed per thread; reused all chunks)
#pragma unroll
        for (int i = 0; i < 4; i++) {
            int r    = (tid + i * 512) >> 4;
            int grow = rowBlk + r;
            gidx[i]  = (grow >> 16) * Mm + idx[grow];
        }

        auto ldgA = [&](int kc) {
#pragma unroll
            for (int i = 0; i < 4; i++) {
                int s  = tid + i * 512;
                int r  = s >> 4;
                int c4 = (s & 15) * 4;
                float4 q = *(const float4*)(query + (size_t)(rowBlk + r) * COUT + kc + c4);
                uint2 gv = *(const uint2*)(g_h2f + (size_t)gidx[i] * COUT + kc + c4);
                float2 ga = __half22float2(*reinterpret_cast<__half2*>(&gv.x));
                float2 gb = __half22float2(*reinterpret_cast<__half2*>(&gv.y));
                vpipe[i] = make_float4(q.x + ga.x, q.y + ga.y, q.z + gb.x, q.w + gb.y);
            }
        };
        auto stsA = [&](int buf) {
            char* ab = smc + buf * A_BYTES;
#pragma unroll
            for (int i = 0; i < 4; i++) {
                int s  = tid + i * 512;
                int r  = s >> 4;
                int c4 = (s & 15) * 4;
                uint32_t h[2];
                round4h(vpipe[i], h);
                *(uint2*)(ab + (r * ASTRE + c4) * 2) = make_uint2(h[0], h[1]);
            }
        };

        float acc[2][8][4];
#pragma unroll
        for (int mi = 0; mi < 2; mi++)
#pragma unroll
            for (int j = 0; j < 8; j++)
#pragma unroll
                for (int c = 0; c < 4; c++) acc[mi][j][c] = 0.f;

        ldgA(0);
        stsA(0);

#pragma unroll 1
        for (int c = 0; c < NC; c++) {
            const int cb = c & 1;
            const bool more = (c + 1 < NC);
            if (more) ldgA((c + 1) * KC);
            __syncthreads();

            const uint32_t aH = sbase + cb * A_BYTES;
            const uint32_t bH = bBase + c * B_BYTES;   // resident chunk c
#pragma unroll
            for (int ks = 0; ks < 4; ks++) {
                const int k0 = ks * 16;
                uint32_t ah[2][4];
#pragma unroll
                for (int mi = 0; mi < 2; mi++)
                    LDSM4(ah[mi], aH + (uint32_t)((wr + mi * 16 + a_r) * ASTRE + k0 + a_kh) * 2);
#pragma unroll
                for (int jp = 0; jp < 4; jp++) {
                    uint32_t bhr[4];
                    LDSM4(bhr, bH + (uint32_t)((wc + jp * 16 + b_r) * ASTRE + k0 + b_kh) * 2);
#pragma unroll
                    for (int mi = 0; mi < 2; mi++)
#pragma unroll
                        for (int jj = 0; jj < 2; jj++)
                            MMA_F16(acc[mi][jp * 2 + jj], ah[mi],
                                    bhr[jj * 2], bhr[jj * 2 + 1]);
                }
            }
            if (more) stsA((c + 1) & 1);
        }

        // ---- epilogue: GN -> fp32 out ----
#pragma unroll
        for (int j = 0; j < 8; j++) {
            const int col = wc + j * 8 + 2 * qlane;
            const float2 bb = *reinterpret_cast<const float2*>(b3 + col);
            const float2 gg = *reinterpret_cast<const float2*>(g3 + col);
            const float2 be = *reinterpret_cast<const float2*>(be3 + col);
#pragma unroll
            for (int mi = 0; mi < 2; mi++) {
                float y0, y1, y2, y3;
                gn8(acc[mi][j][0] + bb.x, acc[mi][j][1] + bb.y,
                    acc[mi][j][2] + bb.x, acc[mi][j][3] + bb.y, gg, be,
                    y0, y1, y2, y3);
                const size_t row = (size_t)rowBlk + wr + mi * 16 + (lane >> 2);
                *reinterpret_cast<float2*>(out + row * COUT + col) =
                    make_float2(y0, y1);
                *reinterpret_cast<float2*>(out + (row + 8) * COUT + col) =
                    make_float2(y2, y3);
            }
        }
        __syncthreads();   // protect A buffers before next block's stsA(0)
    }
}

extern "C" void kernel_launch(void* const* d_in, const int* in_sizes, int n_in,
                              void* d_out, int out_size)
{
    (void)in_sizes; (void)n_in; (void)out_size;
    const float* query   = (const float*)d_in[0];
    const float* support = (const float*)d_in[1];
    const int*   idx     = (const int*)d_in[2];
    const float* W1  = (const float*)d_in[3];
    const float* b1  = (const float*)d_in[4];
    const float* g1  = (const float*)d_in[5];
    const float* be1 = (const float*)d_in[6];
    const float* W2  = (const float*)d_in[7];
    const float* b2  = (const float*)d_in[8];
    const float* g2  = (const float*)d_in[9];
    const float* be2 = (const float*)d_in[10];
    const float* W3  = (const float*)d_in[11];
    const float* b3  = (const float*)d_in[12];
    const float* g3  = (const float*)d_in[13];
    const float* be3 = (const float*)d_in[14];
    float* out = (float*)d_out;

    split_w_kernel<<<CIN,  COUT>>>(W1, 0);
    split_w_kernel<<<COUT, COUT>>>(W2, 1);
    split_w_kernel<<<COUT, COUT>>>(W3, 2);

    cudaFuncSetAttribute(fused12_kernel,
        cudaFuncAttributeMaxDynamicSharedMemorySize, (int)SMEM_F);
    cudaFuncSetAttribute(layer3_kernel,
        cudaFuncAttributeMaxDynamicSharedMemorySize, (int)SMEM_3);

    fused12_kernel<<<ROWS12 / TILE_M, 512, SMEM_F>>>(
        support, b1, g1, be1, b2, g2, be2);
    layer3_kernel<<<GRID3, 512, SMEM_3>>>(
        query, b3, g3, be3, idx, out);
}

// round 12
// speedup vs baseline: 1.3642x; 1.3642x over previous
#include <cuda_runtime.h>
#include <cuda_fp16.h>
#include <cstdint>

// ---------------------------------------------------------------------------
// Upsampling_77214922047593 — legacy mma.sync fp16 single-pass (sm_103 base).
//   fused12:  h2 = unary(unary(support @ W1) @ W2)   65536 rows (h1 in smem)
//   layer3:   out = unary((gather(h2)+query) @ W3)   262144 rows
// R11->R12: REVERT to R10 structure (R11's persistent layer3 benched under a
// ~1.36x clock drift — fused12 regressed with identical code). Single change
// vs R10: weight staging uses cp.async.cg 16B (L2-only, no L1 pollution,
// half the cp.async issue slots).
// ---------------------------------------------------------------------------

namespace {
constexpr int Mm   = 16384;
constexpr int CIN  = 512;
constexpr int COUT = 256;
constexpr float EPSv   = 1e-5f;
constexpr float SLOPEv = 0.1f;

constexpr int ROWS12 = 65536;
constexpr int ROWS3  = 262144;

constexpr int TILE_M = 128;
constexpr int KC     = 64;         // K per smem chunk
constexpr int ASTRE  = 72;         // padded row stride in fp16 elems (144B)

constexpr int A_BYTES   = TILE_M * ASTRE * 2;   // 18432
constexpr int B_BYTES   = COUT   * ASTRE * 2;   // 36864
// fused kernel: A1 double buf + B double buf + A2 (4 chunks, h1 tile)
constexpr size_t SMEM_F = 2 * (size_t)A_BYTES + 2 * B_BYTES + 4 * A_BYTES; // 184320
// layer-3 kernel: (A + B) double buffered
constexpr size_t SMEM_3 = 2 * ((size_t)A_BYTES + B_BYTES);                 // 110592
} // namespace

__device__ __half g_h2f[(size_t)ROWS12 * COUT];     // fp16 h2 (32 MB)
// pre-rounded, pre-transposed weights: Wt[layer][n][k], fp16
__device__ __half g_Wth[3][COUT][CIN];

// ---------------- helpers ----------------
__device__ __forceinline__ uint32_t smem_u32(const void* p) {
    uint32_t a;
    asm("{ .reg .u64 t; cvta.to.shared.u64 t, %1; cvt.u32.u64 %0, t; }"
        : "=r"(a) : "l"(p));
    return a;
}

#define LDSM4(r, addr)                                                         \
    asm volatile("ldmatrix.sync.aligned.m8n8.x4.shared.b16 {%0,%1,%2,%3}, [%4];" \
        : "=r"((r)[0]), "=r"((r)[1]), "=r"((r)[2]), "=r"((r)[3]) : "r"(addr))

#define MMA_F16(c, a, b0, b1)                                                  \
    asm volatile("mma.sync.aligned.m16n8k16.row.col.f32.f16.f16.f32 "          \
        "{%0,%1,%2,%3}, {%4,%5,%6,%7}, {%8,%9}, {%0,%1,%2,%3};"                \
        : "+f"((c)[0]), "+f"((c)[1]), "+f"((c)[2]), "+f"((c)[3])               \
        : "r"((a)[0]), "r"((a)[1]), "r"((a)[2]), "r"((a)[3]),                  \
          "r"(b0), "r"(b1))

// 16-byte L2-only async copy (weights: streamed to smem, never re-read via L1)
#define CP_ASYNC16CG(dst, src)                                                 \
    asm volatile("cp.async.cg.shared.global [%0], [%1], 16;"                   \
        :: "r"(dst), "l"(src))
#define CP_COMMIT() asm volatile("cp.async.commit_group;" ::: "memory")
#define CP_WAIT0()  asm volatile("cp.async.wait_group 0;" ::: "memory")

__device__ __forceinline__ void round4h(float4 v, uint32_t h[2]) {
    __half2 h01 = __floats2half2_rn(v.x, v.y);
    __half2 h23 = __floats2half2_rn(v.z, v.w);
    h[0] = *reinterpret_cast<uint32_t*>(&h01);
    h[1] = *reinterpret_cast<uint32_t*>(&h23);
}

// GroupNorm-of-8 + affine + leaky-relu on one n8 tile's 4 acc values.
__device__ __forceinline__ void gn8(float v0, float v1, float v2, float v3,
                                    float2 gg, float2 be,
                                    float& y0, float& y1, float& y2, float& y3)
{
    float s0 = v0 + v1,           s1 = v2 + v3;
    float t0 = v0 * v0 + v1 * v1, t1 = v2 * v2 + v3 * v3;
    s0 += __shfl_xor_sync(0xffffffffu, s0, 1);
    s0 += __shfl_xor_sync(0xffffffffu, s0, 2);
    s1 += __shfl_xor_sync(0xffffffffu, s1, 1);
    s1 += __shfl_xor_sync(0xffffffffu, s1, 2);
    t0 += __shfl_xor_sync(0xffffffffu, t0, 1);
    t0 += __shfl_xor_sync(0xffffffffu, t0, 2);
    t1 += __shfl_xor_sync(0xffffffffu, t1, 1);
    t1 += __shfl_xor_sync(0xffffffffu, t1, 2);
    const float m0 = s0 * 0.125f, m1 = s1 * 0.125f;
    const float r0 = rsqrtf(fmaxf(t0 * 0.125f - m0 * m0, 0.f) + EPSv);
    const float r1 = rsqrtf(fmaxf(t1 * 0.125f - m1 * m1, 0.f) + EPSv);
    y0 = (v0 - m0) * r0 * gg.x + be.x;
    y1 = (v1 - m0) * r0 * gg.y + be.y;
    y2 = (v2 - m1) * r1 * gg.x + be.x;
    y3 = (v3 - m1) * r1 * gg.y + be.y;
    y0 = (y0 >= 0.f) ? y0 : SLOPEv * y0;
    y1 = (y1 >= 0.f) ? y1 : SLOPEv * y1;
    y2 = (y2 >= 0.f) ? y2 : SLOPEv * y2;
    y3 = (y3 >= 0.f) ? y3 : SLOPEv * y3;
}

// ---------------- weight prologue: round + transpose ----------------
__global__ void split_w_kernel(const float* __restrict__ W, int layer) {
    int k = blockIdx.x;
    int n = threadIdx.x;
    g_Wth[layer][n][k] = __float2half_rn(W[(size_t)k * COUT + n]);
}

// ---------------- fused layers 1+2 ----------------
__global__ void __launch_bounds__(512, 1)
fused12_kernel(const float* __restrict__ support,
               const float* __restrict__ b1, const float* __restrict__ g1,
               const float* __restrict__ be1,
               const float* __restrict__ b2, const float* __restrict__ g2,
               const float* __restrict__ be2)
{
    constexpr int NC1 = CIN / KC;    // 8
    constexpr int NC2 = COUT / KC;   // 4

    extern __shared__ __align__(16) char smc[];
    const uint32_t sbase  = smem_u32(smc);
    const uint32_t bBase  = sbase + 2 * A_BYTES;
    const uint32_t a2Base = bBase + 2 * B_BYTES;
    char* a2c = smc + 2 * A_BYTES + 2 * B_BYTES;

    const int tid  = threadIdx.x;
    const int wid  = tid >> 5;
    const int lane = tid & 31;
    const int rowBlk = blockIdx.x * TILE_M;

    const __half* W1h = &g_Wth[0][0][0];
    const __half* W2h = &g_Wth[1][0][0];

    float4 vpipe[4];
    auto ldgA1 = [&](int kc) {
#pragma unroll
        for (int i = 0; i < 4; i++) {
            int s  = tid + i * 512;
            int r  = s >> 4;
            int c4 = (s & 15) * 4;
            vpipe[i] = *(const float4*)(support + (size_t)(rowBlk + r) * CIN + kc + c4);
        }
    };
    auto stsA1 = [&](int buf) {
        char* ab = smc + buf * A_BYTES;
#pragma unroll
        for (int i = 0; i < 4; i++) {
            int s  = tid + i * 512;
            int r  = s >> 4;
            int c4 = (s & 15) * 4;
            uint32_t h[2];
            round4h(vpipe[i], h);
            *(uint2*)(ab + (r * ASTRE + c4) * 2) = make_uint2(h[0], h[1]);
        }
    };
    // B: 256 n-rows x 8 16B-segs = 2048 segs / 512 thr = 4 each (cg, L2-only)
    auto cpB = [&](const __half* Wsrc, int kc, int buf) {
        uint32_t bh = bBase + buf * B_BYTES;
#pragma unroll
        for (int i = 0; i < 4; i++) {
            int q   = tid + i * 512;
            int n   = q >> 3;
            int seg = q & 7;
            CP_ASYNC16CG(bh + (uint32_t)(n * ASTRE * 2 + seg * 16),
                         Wsrc + (size_t)n * CIN + kc + seg * 8);
        }
    };

    const int wm = wid & 3;
    const int wn = wid >> 2;
    const int wr = wm * 32;
    const int wc = wn * 64;
    const int qlane = lane & 3;

    float acc[2][8][4];
#pragma unroll
    for (int mi = 0; mi < 2; mi++)
#pragma unroll
        for (int j = 0; j < 8; j++)
#pragma unroll
            for (int c = 0; c < 4; c++) acc[mi][j][c] = 0.f;

    const int a_r  = (lane & 15);
    const int a_kh = (lane >> 4) * 8;
    const int b_r  = ((lane >> 4) & 1) * 8 + (lane & 7);
    const int b_kh = ((lane >> 3) & 1) * 8;

    // ================= GEMM 1 (K=512) =================
    ldgA1(0);
    cpB(W1h, 0, 0);
    CP_COMMIT();
    stsA1(0);

#pragma unroll 1
    for (int c = 0; c < NC1; c++) {
        const int cb = c & 1;
        const bool more = (c + 1 < NC1);
        if (more) ldgA1((c + 1) * KC);
        CP_WAIT0();
        __syncthreads();
        if (more) { cpB(W1h, (c + 1) * KC, (c + 1) & 1); CP_COMMIT(); }

        const uint32_t aH = sbase + cb * A_BYTES;
        const uint32_t bH = bBase + cb * B_BYTES;
#pragma unroll
        for (int ks = 0; ks < 4; ks++) {
            const int k0 = ks * 16;
            uint32_t ah[2][4];
#pragma unroll
            for (int mi = 0; mi < 2; mi++)
                LDSM4(ah[mi], aH + (uint32_t)((wr + mi * 16 + a_r) * ASTRE + k0 + a_kh) * 2);
#pragma unroll
            for (int jp = 0; jp < 4; jp++) {
                uint32_t bhr[4];
                LDSM4(bhr, bH + (uint32_t)((wc + jp * 16 + b_r) * ASTRE + k0 + b_kh) * 2);
#pragma unroll
                for (int mi = 0; mi < 2; mi++)
#pragma unroll
                    for (int jj = 0; jj < 2; jj++)
                        MMA_F16(acc[mi][jp * 2 + jj], ah[mi],
                                bhr[jj * 2], bhr[jj * 2 + 1]);
            }
        }
        if (more) stsA1((c + 1) & 1);
    }

    cpB(W2h, 0, 0);
    CP_COMMIT();

    // ---- epilogue 1: GN -> fp16 h1 tile into A2 smem ----
#pragma unroll
    for (int j = 0; j < 8; j++) {
        const int col = wc + j * 8 + 2 * qlane;
        const int kk  = j * 8 + 2 * qlane;
        const float2 bb = *reinterpret_cast<const float2*>(b1 + col);
        const float2 gg = *reinterpret_cast<const float2*>(g1 + col);
        const float2 be = *reinterpret_cast<const float2*>(be1 + col);
#pragma unroll
        for (int mi = 0; mi < 2; mi++) {
            float y0, y1, y2, y3;
            gn8(acc[mi][j][0] + bb.x, acc[mi][j][1] + bb.y,
                acc[mi][j][2] + bb.x, acc[mi][j][3] + bb.y, gg, be,
                y0, y1, y2, y3);
            const int row0 = wr + mi * 16 + (lane >> 2);
            *(__half2*)(a2c + wn * A_BYTES + (row0 * ASTRE + kk) * 2)       = __floats2half2_rn(y0, y1);
            *(__half2*)(a2c + wn * A_BYTES + ((row0 + 8) * ASTRE + kk) * 2) = __floats2half2_rn(y2, y3);
        }
    }

#pragma unroll
    for (int mi = 0; mi < 2; mi++)
#pragma unroll
        for (int j = 0; j < 8; j++)
#pragma unroll
            for (int c = 0; c < 4; c++) acc[mi][j][c] = 0.f;

    __syncthreads();

    // ================= GEMM 2 (K=256, A resident in smem) =================
#pragma unroll 1
    for (int c = 0; c < NC2; c++) {
        const int cb = c & 1;
        const bool more = (c + 1 < NC2);
        CP_WAIT0();
        __syncthreads();
        if (more) { cpB(W2h, (c + 1) * KC, (c + 1) & 1); CP_COMMIT(); }

        const uint32_t aH = a2Base + c * A_BYTES;
        const uint32_t bH = bBase + cb * B_BYTES;
#pragma unroll
        for (int ks = 0; ks < 4; ks++) {
            const int k0 = ks * 16;
            uint32_t ah[2][4];
#pragma unroll
            for (int mi = 0; mi < 2; mi++)
                LDSM4(ah[mi], aH + (uint32_t)((wr + mi * 16 + a_r) * ASTRE + k0 + a_kh) * 2);
#pragma unroll
            for (int jp = 0; jp < 4; jp++) {
                uint32_t bhr[4];
                LDSM4(bhr, bH + (uint32_t)((wc + jp * 16 + b_r) * ASTRE + k0 + b_kh) * 2);
#pragma unroll
                for (int mi = 0; mi < 2; mi++)
#pragma unroll
                    for (int jj = 0; jj < 2; jj++)
                        MMA_F16(acc[mi][jp * 2 + jj], ah[mi],
                                bhr[jj * 2], bhr[jj * 2 + 1]);
            }
        }
    }

    // ---- epilogue 2: GN -> fp16 h2 to global ----
#pragma unroll
    for (int j = 0; j < 8; j++) {
        const int col = wc + j * 8 + 2 * qlane;
        const float2 bb = *reinterpret_cast<const float2*>(b2 + col);
        const float2 gg = *reinterpret_cast<const float2*>(g2 + col);
        const float2 be = *reinterpret_cast<const float2*>(be2 + col);
#pragma unroll
        for (int mi = 0; mi < 2; mi++) {
            float y0, y1, y2, y3;
            gn8(acc[mi][j][0] + bb.x, acc[mi][j][1] + bb.y,
                acc[mi][j][2] + bb.x, acc[mi][j][3] + bb.y, gg, be,
                y0, y1, y2, y3);
            const size_t row = (size_t)rowBlk + wr + mi * 16 + (lane >> 2);
            *(__half2*)(g_h2f + row * COUT + col)       = __floats2half2_rn(y0, y1);
            *(__half2*)(g_h2f + (row + 8) * COUT + col) = __floats2half2_rn(y2, y3);
        }
    }
}

// ---------------- layer 3: out = unary((gather(h2)+query) @ W3) ----------------
__global__ void __launch_bounds__(512, 1)
layer3_kernel(const float* __restrict__ query,
              const float* __restrict__ b3, const float* __restrict__ g3,
              const float* __restrict__ be3,
              const int*   __restrict__ idx,
              float*       __restrict__ out)
{
    constexpr int NC = COUT / KC;   // 4

    extern __shared__ __align__(16) char smc[];
    __shared__ int s_grow[TILE_M];

    const uint32_t sbase = smem_u32(smc);
    const int tid  = threadIdx.x;
    const int wid  = tid >> 5;
    const int lane = tid & 31;
    const int rowBlk = blockIdx.x * TILE_M;

    const __half* W3h = &g_Wth[2][0][0];
    constexpr int BUF_BYTES3 = A_BYTES + B_BYTES;

    if (tid < TILE_M) {
        int grow = rowBlk + tid;
        s_grow[tid] = (grow >> 16) * Mm + idx[grow];
    }
    __syncthreads();

    float4 vpipe[4];
    auto ldgA = [&](int kc) {
#pragma unroll
        for (int i = 0; i < 4; i++) {
            int s  = tid + i * 512;
            int r  = s >> 4;
            int c4 = (s & 15) * 4;
            float4 q = *(const float4*)(query + (size_t)(rowBlk + r) * COUT + kc + c4);
            uint2 gv = *(const uint2*)(g_h2f + (size_t)s_grow[r] * COUT + kc + c4);
            float2 ga = __half22float2(*reinterpret_cast<__half2*>(&gv.x));
            float2 gb = __half22float2(*reinterpret_cast<__half2*>(&gv.y));
            vpipe[i] = make_float4(q.x + ga.x, q.y + ga.y, q.z + gb.x, q.w + gb.y);
        }
    };
    auto stsA = [&](int buf) {
        char* ab = smc + buf * BUF_BYTES3;
#pragma unroll
        for (int i = 0; i < 4; i++) {
            int s  = tid + i * 512;
            int r  = s >> 4;
            int c4 = (s & 15) * 4;
            uint32_t h[2];
            round4h(vpipe[i], h);
            *(uint2*)(ab + (r * ASTRE + c4) * 2) = make_uint2(h[0], h[1]);
        }
    };
    auto cpB = [&](int kc, int buf) {
        uint32_t bh = sbase + buf * BUF_BYTES3 + A_BYTES;
#pragma unroll
        for (int i = 0; i < 4; i++) {
            int q   = tid + i * 512;
            int n   = q >> 3;
            int seg = q & 7;
            CP_ASYNC16CG(bh + (uint32_t)(n * ASTRE * 2 + seg * 16),
                         W3h + (size_t)n * CIN + kc + seg * 8);
        }
    };

    const int wm = wid & 3;
    const int wn = wid >> 2;
    const int wr = wm * 32;
    const int wc = wn * 64;
    const int qlane = lane & 3;

    float acc[2][8][4];
#pragma unroll
    for (int mi = 0; mi < 2; mi++)
#pragma unroll
        for (int j = 0; j < 8; j++)
#pragma unroll
            for (int c = 0; c < 4; c++) acc[mi][j][c] = 0.f;

    const int a_r  = (lane & 15);
    const int a_kh = (lane >> 4) * 8;
    const int b_r  = ((lane >> 4) & 1) * 8 + (lane & 7);
    const int b_kh = ((lane >> 3) & 1) * 8;

    ldgA(0);
    cpB(0, 0);
    CP_COMMIT();
    stsA(0);

#pragma unroll 1
    for (int c = 0; c < NC; c++) {
        const int cb = c & 1;
        const bool more = (c + 1 < NC);
        if (more) ldgA((c + 1) * KC);
        CP_WAIT0();
        __syncthreads();
        if (more) { cpB((c + 1) * KC, (c + 1) & 1); CP_COMMIT(); }

        const uint32_t aH = sbase + cb * BUF_BYTES3;
        const uint32_t bH = aH + A_BYTES;
#pragma unroll
        for (int ks = 0; ks < 4; ks++) {
            const int k0 = ks * 16;
            uint32_t ah[2][4];
#pragma unroll
            for (int mi = 0; mi < 2; mi++)
                LDSM4(ah[mi], aH + (uint32_t)((wr + mi * 16 + a_r) * ASTRE + k0 + a_kh) * 2);
#pragma unroll
            for (int jp = 0; jp < 4; jp++) {
                uint32_t bhr[4];
                LDSM4(bhr, bH + (uint32_t)((wc + jp * 16 + b_r) * ASTRE + k0 + b_kh) * 2);
#pragma unroll
                for (int mi = 0; mi < 2; mi++)
#pragma unroll
                    for (int jj = 0; jj < 2; jj++)
                        MMA_F16(acc[mi][jp * 2 + jj], ah[mi],
                                bhr[jj * 2], bhr[jj * 2 + 1]);
            }
        }
        if (more) stsA((c + 1) & 1);
    }

    // ---- epilogue: GN -> fp32 out ----
#pragma unroll
    for (int j = 0; j < 8; j++) {
        const int col = wc + j * 8 + 2 * qlane;
        const float2 bb = *reinterpret_cast<const float2*>(b3 + col);
        const float2 gg = *reinterpret_cast<const float2*>(g3 + col);
        const float2 be = *reinterpret_cast<const float2*>(be3 + col);
#pragma unroll
        for (int mi = 0; mi < 2; mi++) {
            float y0, y1, y2, y3;
            gn8(acc[mi][j][0] + bb.x, acc[mi][j][1] + bb.y,
                acc[mi][j][2] + bb.x, acc[mi][j][3] + bb.y, gg, be,
                y0, y1, y2, y3);
            const size_t row = (size_t)rowBlk + wr + mi * 16 + (lane >> 2);
            *reinterpret_cast<float2*>(out + row * COUT + col) =
                make_float2(y0, y1);
            *reinterpret_cast<float2*>(out + (row + 8) * COUT + col) =
                make_float2(y2, y3);
        }
    }
}

extern "C" void kernel_launch(void* const* d_in, const int* in_sizes, int n_in,
                              void* d_out, int out_size)
{
    (void)in_sizes; (void)n_in; (void)out_size;
    const float* query   = (const float*)d_in[0];
    const float* support = (const float*)d_in[1];
    const int*   idx     = (const int*)d_in[2];
    const float* W1  = (const float*)d_in[3];
    const float* b1  = (const float*)d_in[4];
    const float* g1  = (const float*)d_in[5];
    const float* be1 = (const float*)d_in[6];
    const float* W2  = (const float*)d_in[7];
    const float* b2  = (const float*)d_in[8];
    const float* g2  = (const float*)d_in[9];
    const float* be2 = (const float*)d_in[10];
    const float* W3  = (const float*)d_in[11];
    const float* b3  = (const float*)d_in[12];
    const float* g3  = (const float*)d_in[13];
    const float* be3 = (const float*)d_in[14];
    float* out = (float*)d_out;

    split_w_kernel<<<CIN,  COUT>>>(W1, 0);
    split_w_kernel<<<COUT, COUT>>>(W2, 1);
    split_w_kernel<<<COUT, COUT>>>(W3, 2);

    cudaFuncSetAttribute(fused12_kernel,
        cudaFuncAttributeMaxDynamicSharedMemorySize, (int)SMEM_F);
    cudaFuncSetAttribute(layer3_kernel,
        cudaFuncAttributeMaxDynamicSharedMemorySize, (int)SMEM_3);

    fused12_kernel<<<ROWS12 / TILE_M, 512, SMEM_F>>>(
        support, b1, g1, be1, b2, g2, be2);
    layer3_kernel<<<ROWS3 / TILE_M, 512, SMEM_3>>>(
        query, b3, g3, be3, idx, out);
}

// round 13
// speedup vs baseline: 1.4538x; 1.0657x over previous
#include <cuda_runtime.h>
#include <cuda_fp16.h>
#include <cstdint>

// ---------------------------------------------------------------------------
// Upsampling_77214922047593 — legacy mma.sync fp16 single-pass (sm_103 base).
//   fused12:  h2 = unary(unary(support @ W1) @ W2)   65536 rows (h1 in smem)
//   layer3:   out = unary((gather(h2)+query) @ W3)   262144 rows
// R12->R13: layer3 switches to TILE_M=64 / 256 threads / 2 CTAs per SM so
// one CTA's MMA region covers the other's prologue, staging and epilogue
// bubbles (layer3 measured ~27% tensor-occupied at 1 CTA/SM).
// fused12 unchanged (near its MMA floor; resident h1 tile needs the smem).
// ---------------------------------------------------------------------------

namespace {
constexpr int Mm   = 16384;
constexpr int CIN  = 512;
constexpr int COUT = 256;
constexpr float EPSv   = 1e-5f;
constexpr float SLOPEv = 0.1f;

constexpr int ROWS12 = 65536;
constexpr int ROWS3  = 262144;

constexpr int TILE_M = 128;        // fused12 tile
constexpr int KC     = 64;         // K per smem chunk
constexpr int ASTRE  = 72;         // padded row stride in fp16 elems (144B)

constexpr int A_BYTES   = TILE_M * ASTRE * 2;   // 18432
constexpr int B_BYTES   = COUT   * ASTRE * 2;   // 36864
// fused kernel: A1 double buf + B double buf + A2 (4 chunks, h1 tile)
constexpr size_t SMEM_F = 2 * (size_t)A_BYTES + 2 * B_BYTES + 4 * A_BYTES; // 184320

// layer-3: TILE_M3=64, 256 threads, 2 CTAs/SM
constexpr int TILE_M3   = 64;
constexpr int A3_BYTES  = TILE_M3 * ASTRE * 2;              // 9216
constexpr int BUF3      = A3_BYTES + B_BYTES;               // 46080
constexpr size_t SMEM_3 = 2 * (size_t)BUF3;                 // 92160 (x2 CTAs = 184320)
} // namespace

__device__ __half g_h2f[(size_t)ROWS12 * COUT];     // fp16 h2 (32 MB)
// pre-rounded, pre-transposed weights: Wt[layer][n][k], fp16
__device__ __half g_Wth[3][COUT][CIN];

// ---------------- helpers ----------------
__device__ __forceinline__ uint32_t smem_u32(const void* p) {
    uint32_t a;
    asm("{ .reg .u64 t; cvta.to.shared.u64 t, %1; cvt.u32.u64 %0, t; }"
        : "=r"(a) : "l"(p));
    return a;
}

#define LDSM4(r, addr)                                                         \
    asm volatile("ldmatrix.sync.aligned.m8n8.x4.shared.b16 {%0,%1,%2,%3}, [%4];" \
        : "=r"((r)[0]), "=r"((r)[1]), "=r"((r)[2]), "=r"((r)[3]) : "r"(addr))

#define MMA_F16(c, a, b0, b1)                                                  \
    asm volatile("mma.sync.aligned.m16n8k16.row.col.f32.f16.f16.f32 "          \
        "{%0,%1,%2,%3}, {%4,%5,%6,%7}, {%8,%9}, {%0,%1,%2,%3};"                \
        : "+f"((c)[0]), "+f"((c)[1]), "+f"((c)[2]), "+f"((c)[3])               \
        : "r"((a)[0]), "r"((a)[1]), "r"((a)[2]), "r"((a)[3]),                  \
          "r"(b0), "r"(b1))

// 16-byte L2-only async copy (weights: streamed to smem, never re-read via L1)
#define CP_ASYNC16CG(dst, src)                                                 \
    asm volatile("cp.async.cg.shared.global [%0], [%1], 16;"                   \
        :: "r"(dst), "l"(src))
#define CP_COMMIT() asm volatile("cp.async.commit_group;" ::: "memory")
#define CP_WAIT0()  asm volatile("cp.async.wait_group 0;" ::: "memory")

__device__ __forceinline__ void round4h(float4 v, uint32_t h[2]) {
    __half2 h01 = __floats2half2_rn(v.x, v.y);
    __half2 h23 = __floats2half2_rn(v.z, v.w);
    h[0] = *reinterpret_cast<uint32_t*>(&h01);
    h[1] = *reinterpret_cast<uint32_t*>(&h23);
}

// GroupNorm-of-8 + affine + leaky-relu on one n8 tile's 4 acc values.
__device__ __forceinline__ void gn8(float v0, float v1, float v2, float v3,
                                    float2 gg, float2 be,
                                    float& y0, float& y1, float& y2, float& y3)
{
    float s0 = v0 + v1,           s1 = v2 + v3;
    float t0 = v0 * v0 + v1 * v1, t1 = v2 * v2 + v3 * v3;
    s0 += __shfl_xor_sync(0xffffffffu, s0, 1);
    s0 += __shfl_xor_sync(0xffffffffu, s0, 2);
    s1 += __shfl_xor_sync(0xffffffffu, s1, 1);
    s1 += __shfl_xor_sync(0xffffffffu, s1, 2);
    t0 += __shfl_xor_sync(0xffffffffu, t0, 1);
    t0 += __shfl_xor_sync(0xffffffffu, t0, 2);
    t1 += __shfl_xor_sync(0xffffffffu, t1, 1);
    t1 += __shfl_xor_sync(0xffffffffu, t1, 2);
    const float m0 = s0 * 0.125f, m1 = s1 * 0.125f;
    const float r0 = rsqrtf(fmaxf(t0 * 0.125f - m0 * m0, 0.f) + EPSv);
    const float r1 = rsqrtf(fmaxf(t1 * 0.125f - m1 * m1, 0.f) + EPSv);
    y0 = (v0 - m0) * r0 * gg.x + be.x;
    y1 = (v1 - m0) * r0 * gg.y + be.y;
    y2 = (v2 - m1) * r1 * gg.x + be.x;
    y3 = (v3 - m1) * r1 * gg.y + be.y;
    y0 = (y0 >= 0.f) ? y0 : SLOPEv * y0;
    y1 = (y1 >= 0.f) ? y1 : SLOPEv * y1;
    y2 = (y2 >= 0.f) ? y2 : SLOPEv * y2;
    y3 = (y3 >= 0.f) ? y3 : SLOPEv * y3;
}

// ---------------- weight prologue: round + transpose ----------------
__global__ void split_w_kernel(const float* __restrict__ W, int layer) {
    int k = blockIdx.x;
    int n = threadIdx.x;
    g_Wth[layer][n][k] = __float2half_rn(W[(size_t)k * COUT + n]);
}

// ---------------- fused layers 1+2 (unchanged from R12) ----------------
__global__ void __launch_bounds__(512, 1)
fused12_kernel(const float* __restrict__ support,
               const float* __restrict__ b1, const float* __restrict__ g1,
               const float* __restrict__ be1,
               const float* __restrict__ b2, const float* __restrict__ g2,
               const float* __restrict__ be2)
{
    constexpr int NC1 = CIN / KC;    // 8
    constexpr int NC2 = COUT / KC;   // 4

    extern __shared__ __align__(16) char smc[];
    const uint32_t sbase  = smem_u32(smc);
    const uint32_t bBase  = sbase + 2 * A_BYTES;
    const uint32_t a2Base = bBase + 2 * B_BYTES;
    char* a2c = smc + 2 * A_BYTES + 2 * B_BYTES;

    const int tid  = threadIdx.x;
    const int wid  = tid >> 5;
    const int lane = tid & 31;
    const int rowBlk = blockIdx.x * TILE_M;

    const __half* W1h = &g_Wth[0][0][0];
    const __half* W2h = &g_Wth[1][0][0];

    float4 vpipe[4];
    auto ldgA1 = [&](int kc) {
#pragma unroll
        for (int i = 0; i < 4; i++) {
            int s  = tid + i * 512;
            int r  = s >> 4;
            int c4 = (s & 15) * 4;
            vpipe[i] = *(const float4*)(support + (size_t)(rowBlk + r) * CIN + kc + c4);
        }
    };
    auto stsA1 = [&](int buf) {
        char* ab = smc + buf * A_BYTES;
#pragma unroll
        for (int i = 0; i < 4; i++) {
            int s  = tid + i * 512;
            int r  = s >> 4;
            int c4 = (s & 15) * 4;
            uint32_t h[2];
            round4h(vpipe[i], h);
            *(uint2*)(ab + (r * ASTRE + c4) * 2) = make_uint2(h[0], h[1]);
        }
    };
    auto cpB = [&](const __half* Wsrc, int kc, int buf) {
        uint32_t bh = bBase + buf * B_BYTES;
#pragma unroll
        for (int i = 0; i < 4; i++) {
            int q   = tid + i * 512;
            int n   = q >> 3;
            int seg = q & 7;
            CP_ASYNC16CG(bh + (uint32_t)(n * ASTRE * 2 + seg * 16),
                         Wsrc + (size_t)n * CIN + kc + seg * 8);
        }
    };

    const int wm = wid & 3;
    const int wn = wid >> 2;
    const int wr = wm * 32;
    const int wc = wn * 64;
    const int qlane = lane & 3;

    float acc[2][8][4];
#pragma unroll
    for (int mi = 0; mi < 2; mi++)
#pragma unroll
        for (int j = 0; j < 8; j++)
#pragma unroll
            for (int c = 0; c < 4; c++) acc[mi][j][c] = 0.f;

    const int a_r  = (lane & 15);
    const int a_kh = (lane >> 4) * 8;
    const int b_r  = ((lane >> 4) & 1) * 8 + (lane & 7);
    const int b_kh = ((lane >> 3) & 1) * 8;

    // ================= GEMM 1 (K=512) =================
    ldgA1(0);
    cpB(W1h, 0, 0);
    CP_COMMIT();
    stsA1(0);

#pragma unroll 1
    for (int c = 0; c < NC1; c++) {
        const int cb = c & 1;
        const bool more = (c + 1 < NC1);
        if (more) ldgA1((c + 1) * KC);
        CP_WAIT0();
        __syncthreads();
        if (more) { cpB(W1h, (c + 1) * KC, (c + 1) & 1); CP_COMMIT(); }

        const uint32_t aH = sbase + cb * A_BYTES;
        const uint32_t bH = bBase + cb * B_BYTES;
#pragma unroll
        for (int ks = 0; ks < 4; ks++) {
            const int k0 = ks * 16;
            uint32_t ah[2][4];
#pragma unroll
            for (int mi = 0; mi < 2; mi++)
                LDSM4(ah[mi], aH + (uint32_t)((wr + mi * 16 + a_r) * ASTRE + k0 + a_kh) * 2);
#pragma unroll
            for (int jp = 0; jp < 4; jp++) {
                uint32_t bhr[4];
                LDSM4(bhr, bH + (uint32_t)((wc + jp * 16 + b_r) * ASTRE + k0 + b_kh) * 2);
#pragma unroll
                for (int mi = 0; mi < 2; mi++)
#pragma unroll
                    for (int jj = 0; jj < 2; jj++)
                        MMA_F16(acc[mi][jp * 2 + jj], ah[mi],
                                bhr[jj * 2], bhr[jj * 2 + 1]);
            }
        }
        if (more) stsA1((c + 1) & 1);
    }

    cpB(W2h, 0, 0);
    CP_COMMIT();

    // ---- epilogue 1: GN -> fp16 h1 tile into A2 smem ----
#pragma unroll
    for (int j = 0; j < 8; j++) {
        const int col = wc + j * 8 + 2 * qlane;
        const int kk  = j * 8 + 2 * qlane;
        const float2 bb = *reinterpret_cast<const float2*>(b1 + col);
        const float2 gg = *reinterpret_cast<const float2*>(g1 + col);
        const float2 be = *reinterpret_cast<const float2*>(be1 + col);
#pragma unroll
        for (int mi = 0; mi < 2; mi++) {
            float y0, y1, y2, y3;
            gn8(acc[mi][j][0] + bb.x, acc[mi][j][1] + bb.y,
                acc[mi][j][2] + bb.x, acc[mi][j][3] + bb.y, gg, be,
                y0, y1, y2, y3);
            const int row0 = wr + mi * 16 + (lane >> 2);
            *(__half2*)(a2c + wn * A_BYTES + (row0 * ASTRE + kk) * 2)       = __floats2half2_rn(y0, y1);
            *(__half2*)(a2c + wn * A_BYTES + ((row0 + 8) * ASTRE + kk) * 2) = __floats2half2_rn(y2, y3);
        }
    }

#pragma unroll
    for (int mi = 0; mi < 2; mi++)
#pragma unroll
        for (int j = 0; j < 8; j++)
#pragma unroll
            for (int c = 0; c < 4; c++) acc[mi][j][c] = 0.f;

    __syncthreads();

    // ================= GEMM 2 (K=256, A resident in smem) =================
#pragma unroll 1
    for (int c = 0; c < NC2; c++) {
        const int cb = c & 1;
        const bool more = (c + 1 < NC2);
        CP_WAIT0();
        __syncthreads();
        if (more) { cpB(W2h, (c + 1) * KC, (c + 1) & 1); CP_COMMIT(); }

        const uint32_t aH = a2Base + c * A_BYTES;
        const uint32_t bH = bBase + cb * B_BYTES;
#pragma unroll
        for (int ks = 0; ks < 4; ks++) {
            const int k0 = ks * 16;
            uint32_t ah[2][4];
#pragma unroll
            for (int mi = 0; mi < 2; mi++)
                LDSM4(ah[mi], aH + (uint32_t)((wr + mi * 16 + a_r) * ASTRE + k0 + a_kh) * 2);
#pragma unroll
            for (int jp = 0; jp < 4; jp++) {
                uint32_t bhr[4];
                LDSM4(bhr, bH + (uint32_t)((wc + jp * 16 + b_r) * ASTRE + k0 + b_kh) * 2);
#pragma unroll
                for (int mi = 0; mi < 2; mi++)
#pragma unroll
                    for (int jj = 0; jj < 2; jj++)
                        MMA_F16(acc[mi][jp * 2 + jj], ah[mi],
                                bhr[jj * 2], bhr[jj * 2 + 1]);
            }
        }
    }

    // ---- epilogue 2: GN -> fp16 h2 to global ----
#pragma unroll
    for (int j = 0; j < 8; j++) {
        const int col = wc + j * 8 + 2 * qlane;
        const float2 bb = *reinterpret_cast<const float2*>(b2 + col);
        const float2 gg = *reinterpret_cast<const float2*>(g2 + col);
        const float2 be = *reinterpret_cast<const float2*>(be2 + col);
#pragma unroll
        for (int mi = 0; mi < 2; mi++) {
            float y0, y1, y2, y3;
            gn8(acc[mi][j][0] + bb.x, acc[mi][j][1] + bb.y,
                acc[mi][j][2] + bb.x, acc[mi][j][3] + bb.y, gg, be,
                y0, y1, y2, y3);
            const size_t row = (size_t)rowBlk + wr + mi * 16 + (lane >> 2);
            *(__half2*)(g_h2f + row * COUT + col)       = __floats2half2_rn(y0, y1);
            *(__half2*)(g_h2f + (row + 8) * COUT + col) = __floats2half2_rn(y2, y3);
        }
    }
}

// ---------------- layer 3: TILE_M3=64, 256 thr, 2 CTAs/SM ----------------
__global__ void __launch_bounds__(256, 2)
layer3_kernel(const float* __restrict__ query,
              const float* __restrict__ b3, const float* __restrict__ g3,
              const float* __restrict__ be3,
              const int*   __restrict__ idx,
              float*       __restrict__ out)
{
    constexpr int NC = COUT / KC;   // 4

    extern __shared__ __align__(16) char smc[];
    __shared__ int s_grow[TILE_M3];

    const uint32_t sbase = smem_u32(smc);
    const int tid  = threadIdx.x;
    const int wid  = tid >> 5;
    const int lane = tid & 31;
    const int rowBlk = blockIdx.x * TILE_M3;

    const __half* W3h = &g_Wth[2][0][0];

    if (tid < TILE_M3) {
        int grow = rowBlk + tid;
        s_grow[tid] = (grow >> 16) * Mm + idx[grow];
    }
    __syncthreads();

    // A: 64 x 64 fp32 = 1024 float4 / 256 thr = 4 each
    float4 vpipe[4];
    auto ldgA = [&](int kc) {
#pragma unroll
        for (int i = 0; i < 4; i++) {
            int s  = tid + i * 256;
            int r  = s >> 4;
            int c4 = (s & 15) * 4;
            float4 q = *(const float4*)(query + (size_t)(rowBlk + r) * COUT + kc + c4);
            uint2 gv = *(const uint2*)(g_h2f + (size_t)s_grow[r] * COUT + kc + c4);
            float2 ga = __half22float2(*reinterpret_cast<__half2*>(&gv.x));
            float2 gb = __half22float2(*reinterpret_cast<__half2*>(&gv.y));
            vpipe[i] = make_float4(q.x + ga.x, q.y + ga.y, q.z + gb.x, q.w + gb.y);
        }
    };
    auto stsA = [&](int buf) {
        char* ab = smc + buf * BUF3;
#pragma unroll
        for (int i = 0; i < 4; i++) {
            int s  = tid + i * 256;
            int r  = s >> 4;
            int c4 = (s & 15) * 4;
            uint32_t h[2];
            round4h(vpipe[i], h);
            *(uint2*)(ab + (r * ASTRE + c4) * 2) = make_uint2(h[0], h[1]);
        }
    };
    // B: 256 n-rows x 8 16B-segs = 2048 / 256 thr = 8 each
    auto cpB = [&](int kc, int buf) {
        uint32_t bh = sbase + buf * BUF3 + A3_BYTES;
#pragma unroll
        for (int i = 0; i < 8; i++) {
            int q   = tid + i * 256;
            int n   = q >> 3;
            int seg = q & 7;
            CP_ASYNC16CG(bh + (uint32_t)(n * ASTRE * 2 + seg * 16),
                         W3h + (size_t)n * CIN + kc + seg * 8);
        }
    };

    // 8 warps = 2 m-groups x 4 n-groups, warp tile 32x64
    const int wr = (wid & 1) * 32;
    const int wc = (wid >> 1) * 64;
    const int qlane = lane & 3;

    float acc[2][8][4];
#pragma unroll
    for (int mi = 0; mi < 2; mi++)
#pragma unroll
        for (int j = 0; j < 8; j++)
#pragma unroll
            for (int c = 0; c < 4; c++) acc[mi][j][c] = 0.f;

    const int a_r  = (lane & 15);
    const int a_kh = (lane >> 4) * 8;
    const int b_r  = ((lane >> 4) & 1) * 8 + (lane & 7);
    const int b_kh = ((lane >> 3) & 1) * 8;

    ldgA(0);
    cpB(0, 0);
    CP_COMMIT();
    stsA(0);

#pragma unroll 1
    for (int c = 0; c < NC; c++) {
        const int cb = c & 1;
        const bool more = (c + 1 < NC);
        if (more) ldgA((c + 1) * KC);
        CP_WAIT0();
        __syncthreads();
        if (more) { cpB((c + 1) * KC, (c + 1) & 1); CP_COMMIT(); }

        const uint32_t aH = sbase + cb * BUF3;
        const uint32_t bH = aH + A3_BYTES;
#pragma unroll
        for (int ks = 0; ks < 4; ks++) {
            const int k0 = ks * 16;
            uint32_t ah[2][4];
#pragma unroll
            for (int mi = 0; mi < 2; mi++)
                LDSM4(ah[mi], aH + (uint32_t)((wr + mi * 16 + a_r) * ASTRE + k0 + a_kh) * 2);
#pragma unroll
            for (int jp = 0; jp < 4; jp++) {
                uint32_t bhr[4];
                LDSM4(bhr, bH + (uint32_t)((wc + jp * 16 + b_r) * ASTRE + k0 + b_kh) * 2);
#pragma unroll
                for (int mi = 0; mi < 2; mi++)
#pragma unroll
                    for (int jj = 0; jj < 2; jj++)
                        MMA_F16(acc[mi][jp * 2 + jj], ah[mi],
                                bhr[jj * 2], bhr[jj * 2 + 1]);
            }
        }
        if (more) stsA((c + 1) & 1);
    }

    // ---- epilogue: GN -> fp32 out ----
#pragma unroll
    for (int j = 0; j < 8; j++) {
        const int col = wc + j * 8 + 2 * qlane;
        const float2 bb = *reinterpret_cast<const float2*>(b3 + col);
        const float2 gg = *reinterpret_cast<const float2*>(g3 + col);
        const float2 be = *reinterpret_cast<const float2*>(be3 + col);
#pragma unroll
        for (int mi = 0; mi < 2; mi++) {
            float y0, y1, y2, y3;
            gn8(acc[mi][j][0] + bb.x, acc[mi][j][1] + bb.y,
                acc[mi][j][2] + bb.x, acc[mi][j][3] + bb.y, gg, be,
                y0, y1, y2, y3);
            const size_t row = (size_t)rowBlk + wr + mi * 16 + (lane >> 2);
            *reinterpret_cast<float2*>(out + row * COUT + col) =
                make_float2(y0, y1);
            *reinterpret_cast<float2*>(out + (row + 8) * COUT + col) =
                make_float2(y2, y3);
        }
    }
}

extern "C" void kernel_launch(void* const* d_in, const int* in_sizes, int n_in,
                              void* d_out, int out_size)
{
    (void)in_sizes; (void)n_in; (void)out_size;
    const float* query   = (const float*)d_in[0];
    const float* support = (const float*)d_in[1];
    const int*   idx     = (const int*)d_in[2];
    const float* W1  = (const float*)d_in[3];
    const float* b1  = (const float*)d_in[4];
    const float* g1  = (const float*)d_in[5];
    const float* be1 = (const float*)d_in[6];
    const float* W2  = (const float*)d_in[7];
    const float* b2  = (const float*)d_in[8];
    const float* g2  = (const float*)d_in[9];
    const float* be2 = (const float*)d_in[10];
    const float* W3  = (const float*)d_in[11];
    const float* b3  = (const float*)d_in[12];
    const float* g3  = (const float*)d_in[13];
    const float* be3 = (const float*)d_in[14];
    float* out = (float*)d_out;

    split_w_kernel<<<CIN,  COUT>>>(W1, 0);
    split_w_kernel<<<COUT, COUT>>>(W2, 1);
    split_w_kernel<<<COUT, COUT>>>(W3, 2);

    cudaFuncSetAttribute(fused12_kernel,
        cudaFuncAttributeMaxDynamicSharedMemorySize, (int)SMEM_F);
    cudaFuncSetAttribute(layer3_kernel,
        cudaFuncAttributeMaxDynamicSharedMemorySize, (int)SMEM_3);

    fused12_kernel<<<ROWS12 / TILE_M, 512, SMEM_F>>>(
        support, b1, g1, be1, b2, g2, be2);
    layer3_kernel<<<ROWS3 / TILE_M3, 256, SMEM_3>>>(
        query, b3, g3, be3, idx, out);
}

// round 14
// speedup vs baseline: 1.4712x; 1.0120x over previous
#include <cuda_runtime.h>
#include <cuda_fp16.h>
#include <cstdint>

// ---------------------------------------------------------------------------
// Upsampling_77214922047593 — legacy mma.sync fp16 single-pass (sm_103 base).
//   fused12:  h2 = unary(unary(support @ W1) @ W2)   65536 rows (h1 in smem)
//   layer3:   out = unary((gather(h2)+query) @ W3)   262144 rows
// R13->R14: fused12 also moves to TILE_M=64 / 256 thr / 2 CTAs per SM
// (KC=32, ASTRE=40; A1 dbl + B dbl + resident h1 tile = 90KB/CTA) so the
// twin CTA covers staging/barrier/epilogue bubbles — the mechanism that won
// R13 for layer3. layer3 unchanged from R13. split_w prologue merged to one
// launch.
// ---------------------------------------------------------------------------

namespace {
constexpr int Mm   = 16384;
constexpr int CIN  = 512;
constexpr int COUT = 256;
constexpr float EPSv   = 1e-5f;
constexpr float SLOPEv = 0.1f;

constexpr int ROWS12 = 65536;
constexpr int ROWS3  = 262144;

// ---- fused12 geometry (TILE 64x256, KC=32, 2 CTAs/SM) ----
constexpr int TM12   = 64;
constexpr int KC12   = 32;
constexpr int AST12  = 40;                       // fp16 elems (80B rows)
constexpr int A1B    = TM12 * AST12 * 2;         // 5120
constexpr int B12B   = COUT * AST12 * 2;         // 20480
constexpr int A2OFF  = 2 * A1B + 2 * B12B;       // 51200
constexpr size_t SMEM_F = A2OFF + 8 * A1B;       // 92160 (x2 CTAs = 184320)

// ---- layer3 geometry (TILE 64x256, KC=64, 2 CTAs/SM) — unchanged R13 ----
constexpr int TILE_M3 = 64;
constexpr int KC3     = 64;
constexpr int ASTRE   = 72;                      // fp16 elems (144B rows)
constexpr int A3_BYTES = TILE_M3 * ASTRE * 2;    // 9216
constexpr int B3_BYTES = COUT * ASTRE * 2;       // 36864
constexpr int BUF3     = A3_BYTES + B3_BYTES;    // 46080
constexpr size_t SMEM_3 = 2 * (size_t)BUF3;      // 92160
} // namespace

__device__ __half g_h2f[(size_t)ROWS12 * COUT];     // fp16 h2 (32 MB)
__device__ __half g_Wth[3][COUT][CIN];              // rounded, transposed weights

// ---------------- helpers ----------------
__device__ __forceinline__ uint32_t smem_u32(const void* p) {
    uint32_t a;
    asm("{ .reg .u64 t; cvta.to.shared.u64 t, %1; cvt.u32.u64 %0, t; }"
        : "=r"(a) : "l"(p));
    return a;
}

#define LDSM4(r, addr)                                                         \
    asm volatile("ldmatrix.sync.aligned.m8n8.x4.shared.b16 {%0,%1,%2,%3}, [%4];" \
        : "=r"((r)[0]), "=r"((r)[1]), "=r"((r)[2]), "=r"((r)[3]) : "r"(addr))

#define MMA_F16(c, a, b0, b1)                                                  \
    asm volatile("mma.sync.aligned.m16n8k16.row.col.f32.f16.f16.f32 "          \
        "{%0,%1,%2,%3}, {%4,%5,%6,%7}, {%8,%9}, {%0,%1,%2,%3};"                \
        : "+f"((c)[0]), "+f"((c)[1]), "+f"((c)[2]), "+f"((c)[3])               \
        : "r"((a)[0]), "r"((a)[1]), "r"((a)[2]), "r"((a)[3]),                  \
          "r"(b0), "r"(b1))

#define CP_ASYNC16CG(dst, src)                                                 \
    asm volatile("cp.async.cg.shared.global [%0], [%1], 16;"                   \
        :: "r"(dst), "l"(src))
#define CP_COMMIT() asm volatile("cp.async.commit_group;" ::: "memory")
#define CP_WAIT0()  asm volatile("cp.async.wait_group 0;" ::: "memory")

__device__ __forceinline__ void round4h(float4 v, uint32_t h[2]) {
    __half2 h01 = __floats2half2_rn(v.x, v.y);
    __half2 h23 = __floats2half2_rn(v.z, v.w);
    h[0] = *reinterpret_cast<uint32_t*>(&h01);
    h[1] = *reinterpret_cast<uint32_t*>(&h23);
}

// GroupNorm-of-8 + affine + leaky-relu on one n8 tile's 4 acc values.
__device__ __forceinline__ void gn8(float v0, float v1, float v2, float v3,
                                    float2 gg, float2 be,
                                    float& y0, float& y1, float& y2, float& y3)
{
    float s0 = v0 + v1,           s1 = v2 + v3;
    float t0 = v0 * v0 + v1 * v1, t1 = v2 * v2 + v3 * v3;
    s0 += __shfl_xor_sync(0xffffffffu, s0, 1);
    s0 += __shfl_xor_sync(0xffffffffu, s0, 2);
    s1 += __shfl_xor_sync(0xffffffffu, s1, 1);
    s1 += __shfl_xor_sync(0xffffffffu, s1, 2);
    t0 += __shfl_xor_sync(0xffffffffu, t0, 1);
    t0 += __shfl_xor_sync(0xffffffffu, t0, 2);
    t1 += __shfl_xor_sync(0xffffffffu, t1, 1);
    t1 += __shfl_xor_sync(0xffffffffu, t1, 2);
    const float m0 = s0 * 0.125f, m1 = s1 * 0.125f;
    const float r0 = rsqrtf(fmaxf(t0 * 0.125f - m0 * m0, 0.f) + EPSv);
    const float r1 = rsqrtf(fmaxf(t1 * 0.125f - m1 * m1, 0.f) + EPSv);
    y0 = (v0 - m0) * r0 * gg.x + be.x;
    y1 = (v1 - m0) * r0 * gg.y + be.y;
    y2 = (v2 - m1) * r1 * gg.x + be.x;
    y3 = (v3 - m1) * r1 * gg.y + be.y;
    y0 = (y0 >= 0.f) ? y0 : SLOPEv * y0;
    y1 = (y1 >= 0.f) ? y1 : SLOPEv * y1;
    y2 = (y2 >= 0.f) ? y2 : SLOPEv * y2;
    y3 = (y3 >= 0.f) ? y3 : SLOPEv * y3;
}

// ---------------- weight prologue: round + transpose (one launch) ----------
__global__ void split_w_all(const float* __restrict__ W1,
                            const float* __restrict__ W2,
                            const float* __restrict__ W3)
{
    int b = blockIdx.x;
    int n = threadIdx.x;
    const float* W;
    int layer, k;
    if (b < CIN)              { W = W1; layer = 0; k = b; }
    else if (b < CIN + COUT)  { W = W2; layer = 1; k = b - CIN; }
    else                      { W = W3; layer = 2; k = b - CIN - COUT; }
    g_Wth[layer][n][k] = __float2half_rn(W[(size_t)k * COUT + n]);
}

// ---------------- fused layers 1+2: 64x256 tile, 2 CTAs/SM ----------------
__global__ void __launch_bounds__(256, 2)
fused12_kernel(const float* __restrict__ support,
               const float* __restrict__ b1, const float* __restrict__ g1,
               const float* __restrict__ be1,
               const float* __restrict__ b2, const float* __restrict__ g2,
               const float* __restrict__ be2)
{
    constexpr int NC1 = CIN / KC12;    // 16
    constexpr int NC2 = COUT / KC12;   // 8

    extern __shared__ __align__(16) char smc[];
    const uint32_t sbase  = smem_u32(smc);
    const uint32_t bBase  = sbase + 2 * A1B;
    const uint32_t a2Base = sbase + A2OFF;
    char* a2c = smc + A2OFF;

    const int tid  = threadIdx.x;
    const int wid  = tid >> 5;
    const int lane = tid & 31;
    const int rowBlk = blockIdx.x * TM12;

    const __half* W1h = &g_Wth[0][0][0];
    const __half* W2h = &g_Wth[1][0][0];

    // A1: 64 rows x 32 fp32 = 512 float4 / 256 thr = 2 each
    float4 vpipe[2];
    auto ldgA1 = [&](int kc) {
#pragma unroll
        for (int i = 0; i < 2; i++) {
            int s  = tid + i * 256;
            int r  = s >> 3;
            int c4 = (s & 7) * 4;
            vpipe[i] = *(const float4*)(support + (size_t)(rowBlk + r) * CIN + kc + c4);
        }
    };
    auto stsA1 = [&](int buf) {
        char* ab = smc + buf * A1B;
#pragma unroll
        for (int i = 0; i < 2; i++) {
            int s  = tid + i * 256;
            int r  = s >> 3;
            int c4 = (s & 7) * 4;
            uint32_t h[2];
            round4h(vpipe[i], h);
            *(uint2*)(ab + (r * AST12 + c4) * 2) = make_uint2(h[0], h[1]);
        }
    };
    // B: 256 n-rows x 4 16B-segs = 1024 segs / 256 thr = 4 each (cg, L2-only)
    auto cpB = [&](const __half* Wsrc, int kc, int buf) {
        uint32_t bh = bBase + buf * B12B;
#pragma unroll
        for (int i = 0; i < 4; i++) {
            int q   = tid + i * 256;
            int n   = q >> 2;
            int seg = q & 3;
            CP_ASYNC16CG(bh + (uint32_t)(n * AST12 * 2 + seg * 16),
                         Wsrc + (size_t)n * CIN + kc + seg * 8);
        }
    };

    // 8 warps = 2 m-groups x 4 n-groups, warp tile 32x64
    const int wr = (wid & 1) * 32;
    const int wc = (wid >> 1) * 64;
    const int qlane = lane & 3;

    float acc[2][8][4];
#pragma unroll
    for (int mi = 0; mi < 2; mi++)
#pragma unroll
        for (int j = 0; j < 8; j++)
#pragma unroll
            for (int c = 0; c < 4; c++) acc[mi][j][c] = 0.f;

    const int a_r  = (lane & 15);
    const int a_kh = (lane >> 4) * 8;
    const int b_r  = ((lane >> 4) & 1) * 8 + (lane & 7);
    const int b_kh = ((lane >> 3) & 1) * 8;

    // ================= GEMM 1 (K=512, 16 chunks of 32) =================
    ldgA1(0);
    cpB(W1h, 0, 0);
    CP_COMMIT();
    stsA1(0);

#pragma unroll 1
    for (int c = 0; c < NC1; c++) {
        const int cb = c & 1;
        const bool more = (c + 1 < NC1);
        if (more) ldgA1((c + 1) * KC12);
        CP_WAIT0();
        __syncthreads();
        if (more) { cpB(W1h, (c + 1) * KC12, (c + 1) & 1); CP_COMMIT(); }

        const uint32_t aH = sbase + cb * A1B;
        const uint32_t bH = bBase + cb * B12B;
#pragma unroll
        for (int ks = 0; ks < 2; ks++) {
            const int k0 = ks * 16;
            uint32_t ah[2][4];
#pragma unroll
            for (int mi = 0; mi < 2; mi++)
                LDSM4(ah[mi], aH + (uint32_t)((wr + mi * 16 + a_r) * AST12 + k0 + a_kh) * 2);
#pragma unroll
            for (int jp = 0; jp < 4; jp++) {
                uint32_t bhr[4];
                LDSM4(bhr, bH + (uint32_t)((wc + jp * 16 + b_r) * AST12 + k0 + b_kh) * 2);
#pragma unroll
                for (int mi = 0; mi < 2; mi++)
#pragma unroll
                    for (int jj = 0; jj < 2; jj++)
                        MMA_F16(acc[mi][jp * 2 + jj], ah[mi],
                                bhr[jj * 2], bhr[jj * 2 + 1]);
            }
        }
        if (more) stsA1((c + 1) & 1);
    }

    cpB(W2h, 0, 0);
    CP_COMMIT();

    // ---- epilogue 1: GN -> fp16 h1 tile into A2 (8 chunks of 64x32) ----
    // col = wc + j*8 + 2*qlane; chunk = wn*2 + (j>>2); kk = (j&3)*8 + 2*qlane
#pragma unroll
    for (int j = 0; j < 8; j++) {
        const int col = wc + j * 8 + 2 * qlane;
        const int ch  = (wid >> 1) * 2 + (j >> 2);
        const int kk  = (j & 3) * 8 + 2 * qlane;
        const float2 bb = *reinterpret_cast<const float2*>(b1 + col);
        const float2 gg = *reinterpret_cast<const float2*>(g1 + col);
        const float2 be = *reinterpret_cast<const float2*>(be1 + col);
#pragma unroll
        for (int mi = 0; mi < 2; mi++) {
            float y0, y1, y2, y3;
            gn8(acc[mi][j][0] + bb.x, acc[mi][j][1] + bb.y,
                acc[mi][j][2] + bb.x, acc[mi][j][3] + bb.y, gg, be,
                y0, y1, y2, y3);
            const int row0 = wr + mi * 16 + (lane >> 2);
            *(__half2*)(a2c + ch * A1B + (row0 * AST12 + kk) * 2)       = __floats2half2_rn(y0, y1);
            *(__half2*)(a2c + ch * A1B + ((row0 + 8) * AST12 + kk) * 2) = __floats2half2_rn(y2, y3);
        }
    }

#pragma unroll
    for (int mi = 0; mi < 2; mi++)
#pragma unroll
        for (int j = 0; j < 8; j++)
#pragma unroll
            for (int c = 0; c < 4; c++) acc[mi][j][c] = 0.f;

    __syncthreads();

    // ================= GEMM 2 (K=256, 8 chunks, A resident) =================
#pragma unroll 1
    for (int c = 0; c < NC2; c++) {
        const int cb = c & 1;
        const bool more = (c + 1 < NC2);
        CP_WAIT0();
        __syncthreads();
        if (more) { cpB(W2h, (c + 1) * KC12, (c + 1) & 1); CP_COMMIT(); }

        const uint32_t aH = a2Base + c * A1B;
        const uint32_t bH = bBase + cb * B12B;
#pragma unroll
        for (int ks = 0; ks < 2; ks++) {
            const int k0 = ks * 16;
            uint32_t ah[2][4];
#pragma unroll
            for (int mi = 0; mi < 2; mi++)
                LDSM4(ah[mi], aH + (uint32_t)((wr + mi * 16 + a_r) * AST12 + k0 + a_kh) * 2);
#pragma unroll
            for (int jp = 0; jp < 4; jp++) {
                uint32_t bhr[4];
                LDSM4(bhr, bH + (uint32_t)((wc + jp * 16 + b_r) * AST12 + k0 + b_kh) * 2);
#pragma unroll
                for (int mi = 0; mi < 2; mi++)
#pragma unroll
                    for (int jj = 0; jj < 2; jj++)
                        MMA_F16(acc[mi][jp * 2 + jj], ah[mi],
                                bhr[jj * 2], bhr[jj * 2 + 1]);
            }
        }
    }

    // ---- epilogue 2: GN -> fp16 h2 to global ----
#pragma unroll
    for (int j = 0; j < 8; j++) {
        const int col = wc + j * 8 + 2 * qlane;
        const float2 bb = *reinterpret_cast<const float2*>(b2 + col);
        const float2 gg = *reinterpret_cast<const float2*>(g2 + col);
        const float2 be = *reinterpret_cast<const float2*>(be2 + col);
#pragma unroll
        for (int mi = 0; mi < 2; mi++) {
            float y0, y1, y2, y3;
            gn8(acc[mi][j][0] + bb.x, acc[mi][j][1] + bb.y,
                acc[mi][j][2] + bb.x, acc[mi][j][3] + bb.y, gg, be,
                y0, y1, y2, y3);
            const size_t row = (size_t)rowBlk + wr + mi * 16 + (lane >> 2);
            *(__half2*)(g_h2f + row * COUT + col)       = __floats2half2_rn(y0, y1);
            *(__half2*)(g_h2f + (row + 8) * COUT + col) = __floats2half2_rn(y2, y3);
        }
    }
}

// ---------------- layer 3: TILE_M3=64, 256 thr, 2 CTAs/SM (R13) -----------
__global__ void __launch_bounds__(256, 2)
layer3_kernel(const float* __restrict__ query,
              const float* __restrict__ b3, const float* __restrict__ g3,
              const float* __restrict__ be3,
              const int*   __restrict__ idx,
              float*       __restrict__ out)
{
    constexpr int NC = COUT / KC3;   // 4

    extern __shared__ __align__(16) char smc[];
    __shared__ int s_grow[TILE_M3];

    const uint32_t sbase = smem_u32(smc);
    const int tid  = threadIdx.x;
    const int wid  = tid >> 5;
    const int lane = tid & 31;
    const int rowBlk = blockIdx.x * TILE_M3;

    const __half* W3h = &g_Wth[2][0][0];

    if (tid < TILE_M3) {
        int grow = rowBlk + tid;
        s_grow[tid] = (grow >> 16) * Mm + idx[grow];
    }
    __syncthreads();

    float4 vpipe[4];
    auto ldgA = [&](int kc) {
#pragma unroll
        for (int i = 0; i < 4; i++) {
            int s  = tid + i * 256;
            int r  = s >> 4;
            int c4 = (s & 15) * 4;
            float4 q = *(const float4*)(query + (size_t)(rowBlk + r) * COUT + kc + c4);
            uint2 gv = *(const uint2*)(g_h2f + (size_t)s_grow[r] * COUT + kc + c4);
            float2 ga = __half22float2(*reinterpret_cast<__half2*>(&gv.x));
            float2 gb = __half22float2(*reinterpret_cast<__half2*>(&gv.y));
            vpipe[i] = make_float4(q.x + ga.x, q.y + ga.y, q.z + gb.x, q.w + gb.y);
        }
    };
    auto stsA = [&](int buf) {
        char* ab = smc + buf * BUF3;
#pragma unroll
        for (int i = 0; i < 4; i++) {
            int s  = tid + i * 256;
            int r  = s >> 4;
            int c4 = (s & 15) * 4;
            uint32_t h[2];
            round4h(vpipe[i], h);
            *(uint2*)(ab + (r * ASTRE + c4) * 2) = make_uint2(h[0], h[1]);
        }
    };
    auto cpB = [&](int kc, int buf) {
        uint32_t bh = sbase + buf * BUF3 + A3_BYTES;
#pragma unroll
        for (int i = 0; i < 8; i++) {
            int q   = tid + i * 256;
            int n   = q >> 3;
            int seg = q & 7;
            CP_ASYNC16CG(bh + (uint32_t)(n * ASTRE * 2 + seg * 16),
                         W3h + (size_t)n * CIN + kc + seg * 8);
        }
    };

    const int wr = (wid & 1) * 32;
    const int wc = (wid >> 1) * 64;
    const int qlane = lane & 3;

    float acc[2][8][4];
#pragma unroll
    for (int mi = 0; mi < 2; mi++)
#pragma unroll
        for (int j = 0; j < 8; j++)
#pragma unroll
            for (int c = 0; c < 4; c++) acc[mi][j][c] = 0.f;

    const int a_r  = (lane & 15);
    const int a_kh = (lane >> 4) * 8;
    const int b_r  = ((lane >> 4) & 1) * 8 + (lane & 7);
    const int b_kh = ((lane >> 3) & 1) * 8;

    ldgA(0);
    cpB(0, 0);
    CP_COMMIT();
    stsA(0);

#pragma unroll 1
    for (int c = 0; c < NC; c++) {
        const int cb = c & 1;
        const bool more = (c + 1 < NC);
        if (more) ldgA((c + 1) * KC3);
        CP_WAIT0();
        __syncthreads();
        if (more) { cpB((c + 1) * KC3, (c + 1) & 1); CP_COMMIT(); }

        const uint32_t aH = sbase + cb * BUF3;
        const uint32_t bH = aH + A3_BYTES;
#pragma unroll
        for (int ks = 0; ks < 4; ks++) {
            const int k0 = ks * 16;
            uint32_t ah[2][4];
#pragma unroll
            for (int mi = 0; mi < 2; mi++)
                LDSM4(ah[mi], aH + (uint32_t)((wr + mi * 16 + a_r) * ASTRE + k0 + a_kh) * 2);
#pragma unroll
            for (int jp = 0; jp < 4; jp++) {
                uint32_t bhr[4];
                LDSM4(bhr, bH + (uint32_t)((wc + jp * 16 + b_r) * ASTRE + k0 + b_kh) * 2);
#pragma unroll
                for (int mi = 0; mi < 2; mi++)
#pragma unroll
                    for (int jj = 0; jj < 2; jj++)
                        MMA_F16(acc[mi][jp * 2 + jj], ah[mi],
                                bhr[jj * 2], bhr[jj * 2 + 1]);
            }
        }
        if (more) stsA((c + 1) & 1);
    }

    // ---- epilogue: GN -> fp32 out ----
#pragma unroll
    for (int j = 0; j < 8; j++) {
        const int col = wc + j * 8 + 2 * qlane;
        const float2 bb = *reinterpret_cast<const float2*>(b3 + col);
        const float2 gg = *reinterpret_cast<const float2*>(g3 + col);
        const float2 be = *reinterpret_cast<const float2*>(be3 + col);
#pragma unroll
        for (int mi = 0; mi < 2; mi++) {
            float y0, y1, y2, y3;
            gn8(acc[mi][j][0] + bb.x, acc[mi][j][1] + bb.y,
                acc[mi][j][2] + bb.x, acc[mi][j][3] + bb.y, gg, be,
                y0, y1, y2, y3);
            const size_t row = (size_t)rowBlk + wr + mi * 16 + (lane >> 2);
            *reinterpret_cast<float2*>(out + row * COUT + col) =
                make_float2(y0, y1);
            *reinterpret_cast<float2*>(out + (row + 8) * COUT + col) =
                make_float2(y2, y3);
        }
    }
}

extern "C" void kernel_launch(void* const* d_in, const int* in_sizes, int n_in,
                              void* d_out, int out_size)
{
    (void)in_sizes; (void)n_in; (void)out_size;
    const float* query   = (const float*)d_in[0];
    const float* support = (const float*)d_in[1];
    const int*   idx     = (const int*)d_in[2];
    const float* W1  = (const float*)d_in[3];
    const float* b1  = (const float*)d_in[4];
    const float* g1  = (const float*)d_in[5];
    const float* be1 = (const float*)d_in[6];
    const float* W2  = (const float*)d_in[7];
    const float* b2  = (const float*)d_in[8];
    const float* g2  = (const float*)d_in[9];
    const float* be2 = (const float*)d_in[10];
    const float* W3  = (const float*)d_in[11];
    const float* b3  = (const float*)d_in[12];
    const float* g3  = (const float*)d_in[13];
    const float* be3 = (const float*)d_in[14];
    float* out = (float*)d_out;

    split_w_all<<<CIN + COUT + COUT, COUT>>>(W1, W2, W3);

    cudaFuncSetAttribute(fused12_kernel,
        cudaFuncAttributeMaxDynamicSharedMemorySize, (int)SMEM_F);
    cudaFuncSetAttribute(layer3_kernel,
        cudaFuncAttributeMaxDynamicSharedMemorySize, (int)SMEM_3);

    fused12_kernel<<<ROWS12 / TM12, 256, SMEM_F>>>(
        support, b1, g1, be1, b2, g2, be2);
    layer3_kernel<<<ROWS3 / TILE_M3, 256, SMEM_3>>>(
        query, b3, g3, be3, idx, out);
}

// round 15
// speedup vs baseline: 1.4937x; 1.0153x over previous
#include <cuda_runtime.h>
#include <cuda_fp16.h>
#include <cstdint>

// ---------------------------------------------------------------------------
// Upsampling_77214922047593 — legacy mma.sync fp16 single-pass (sm_103 base).
//   fused12:  h2 = unary(unary(support @ W1) @ W2)   65536 rows (h1 in smem)
//   layer3:   out = unary((gather(h2)+query) @ W3)   262144 rows
// R14->R15 (harvesting the last identified slack; HMMA fp32-acc rate
// ~224 TF/s is treated as the hardware floor => ~269us MMA floor):
//  * split_w: 32x32 smem-tile transpose (was fully uncoalesced, 6.8us -> ~1.5)
//  * __ldcs on support/query (read-once streams), __stcs on out (write-once)
//    so the 32MB h2 stays L2-resident for layer3's gather.
// ---------------------------------------------------------------------------

namespace {
constexpr int Mm   = 16384;
constexpr int CIN  = 512;
constexpr int COUT = 256;
constexpr float EPSv   = 1e-5f;
constexpr float SLOPEv = 0.1f;

constexpr int ROWS12 = 65536;
constexpr int ROWS3  = 262144;

// ---- fused12 geometry (TILE 64x256, KC=32, 2 CTAs/SM) ----
constexpr int TM12   = 64;
constexpr int KC12   = 32;
constexpr int AST12  = 40;                       // fp16 elems (80B rows)
constexpr int A1B    = TM12 * AST12 * 2;         // 5120
constexpr int B12B   = COUT * AST12 * 2;         // 20480
constexpr int A2OFF  = 2 * A1B + 2 * B12B;       // 51200
constexpr size_t SMEM_F = A2OFF + 8 * A1B;       // 92160 (x2 CTAs = 184320)

// ---- layer3 geometry (TILE 64x256, KC=64, 2 CTAs/SM) ----
constexpr int TILE_M3 = 64;
constexpr int KC3     = 64;
constexpr int ASTRE   = 72;                      // fp16 elems (144B rows)
constexpr int A3_BYTES = TILE_M3 * ASTRE * 2;    // 9216
constexpr int B3_BYTES = COUT * ASTRE * 2;       // 36864
constexpr int BUF3     = A3_BYTES + B3_BYTES;    // 46080
constexpr size_t SMEM_3 = 2 * (size_t)BUF3;      // 92160
} // namespace

__device__ __half g_h2f[(size_t)ROWS12 * COUT];     // fp16 h2 (32 MB)
__device__ __half g_Wth[3][COUT][CIN];              // rounded, transposed weights

// ---------------- helpers ----------------
__device__ __forceinline__ uint32_t smem_u32(const void* p) {
    uint32_t a;
    asm("{ .reg .u64 t; cvta.to.shared.u64 t, %1; cvt.u32.u64 %0, t; }"
        : "=r"(a) : "l"(p));
    return a;
}

#define LDSM4(r, addr)                                                         \
    asm volatile("ldmatrix.sync.aligned.m8n8.x4.shared.b16 {%0,%1,%2,%3}, [%4];" \
        : "=r"((r)[0]), "=r"((r)[1]), "=r"((r)[2]), "=r"((r)[3]) : "r"(addr))

#define MMA_F16(c, a, b0, b1)                                                  \
    asm volatile("mma.sync.aligned.m16n8k16.row.col.f32.f16.f16.f32 "          \
        "{%0,%1,%2,%3}, {%4,%5,%6,%7}, {%8,%9}, {%0,%1,%2,%3};"                \
        : "+f"((c)[0]), "+f"((c)[1]), "+f"((c)[2]), "+f"((c)[3])               \
        : "r"((a)[0]), "r"((a)[1]), "r"((a)[2]), "r"((a)[3]),                  \
          "r"(b0), "r"(b1))

#define CP_ASYNC16CG(dst, src)                                                 \
    asm volatile("cp.async.cg.shared.global [%0], [%1], 16;"                   \
        :: "r"(dst), "l"(src))
#define CP_COMMIT() asm volatile("cp.async.commit_group;" ::: "memory")
#define CP_WAIT0()  asm volatile("cp.async.wait_group 0;" ::: "memory")

__device__ __forceinline__ void round4h(float4 v, uint32_t h[2]) {
    __half2 h01 = __floats2half2_rn(v.x, v.y);
    __half2 h23 = __floats2half2_rn(v.z, v.w);
    h[0] = *reinterpret_cast<uint32_t*>(&h01);
    h[1] = *reinterpret_cast<uint32_t*>(&h23);
}

// GroupNorm-of-8 + affine + leaky-relu on one n8 tile's 4 acc values.
__device__ __forceinline__ void gn8(float v0, float v1, float v2, float v3,
                                    float2 gg, float2 be,
                                    float& y0, float& y1, float& y2, float& y3)
{
    float s0 = v0 + v1,           s1 = v2 + v3;
    float t0 = v0 * v0 + v1 * v1, t1 = v2 * v2 + v3 * v3;
    s0 += __shfl_xor_sync(0xffffffffu, s0, 1);
    s0 += __shfl_xor_sync(0xffffffffu, s0, 2);
    s1 += __shfl_xor_sync(0xffffffffu, s1, 1);
    s1 += __shfl_xor_sync(0xffffffffu, s1, 2);
    t0 += __shfl_xor_sync(0xffffffffu, t0, 1);
    t0 += __shfl_xor_sync(0xffffffffu, t0, 2);
    t1 += __shfl_xor_sync(0xffffffffu, t1, 1);
    t1 += __shfl_xor_sync(0xffffffffu, t1, 2);
    const float m0 = s0 * 0.125f, m1 = s1 * 0.125f;
    const float r0 = rsqrtf(fmaxf(t0 * 0.125f - m0 * m0, 0.f) + EPSv);
    const float r1 = rsqrtf(fmaxf(t1 * 0.125f - m1 * m1, 0.f) + EPSv);
    y0 = (v0 - m0) * r0 * gg.x + be.x;
    y1 = (v1 - m0) * r0 * gg.y + be.y;
    y2 = (v2 - m1) * r1 * gg.x + be.x;
    y3 = (v3 - m1) * r1 * gg.y + be.y;
    y0 = (y0 >= 0.f) ? y0 : SLOPEv * y0;
    y1 = (y1 >= 0.f) ? y1 : SLOPEv * y1;
    y2 = (y2 >= 0.f) ? y2 : SLOPEv * y2;
    y3 = (y3 >= 0.f) ? y3 : SLOPEv * y3;
}

// ---------------- weight prologue: coalesced smem-tile transpose -----------
// 32x32 tiles; read W[k][n] coalesced, write g_Wth[layer][n][k] coalesced.
__global__ void split_w_all(const float* __restrict__ W1,
                            const float* __restrict__ W2,
                            const float* __restrict__ W3)
{
    __shared__ __half tile[32][33];
    int b = blockIdx.x;            // 0..255
    const float* W;
    int layer, kt, nt;
    if (b < 128)      { W = W1; layer = 0; kt = b >> 3;        nt = b & 7; }
    else if (b < 192) { W = W2; layer = 1; kt = (b - 128) >> 3; nt = b & 7; }
    else              { W = W3; layer = 2; kt = (b - 192) >> 3; nt = b & 7; }

    const int tx = threadIdx.x & 31;
    const int ty = threadIdx.x >> 5;   // 0..7

#pragma unroll
    for (int r = 0; r < 4; r++) {
        int k = kt * 32 + ty + r * 8;
        int n = nt * 32 + tx;
        tile[ty + r * 8][tx] = __float2half_rn(W[(size_t)k * COUT + n]);
    }
    __syncthreads();
#pragma unroll
    for (int r = 0; r < 4; r++) {
        int n = nt * 32 + ty + r * 8;
        int k = kt * 32 + tx;
        g_Wth[layer][n][k] = tile[tx][ty + r * 8];
    }
}

// ---------------- fused layers 1+2: 64x256 tile, 2 CTAs/SM ----------------
__global__ void __launch_bounds__(256, 2)
fused12_kernel(const float* __restrict__ support,
               const float* __restrict__ b1, const float* __restrict__ g1,
               const float* __restrict__ be1,
               const float* __restrict__ b2, const float* __restrict__ g2,
               const float* __restrict__ be2)
{
    constexpr int NC1 = CIN / KC12;    // 16
    constexpr int NC2 = COUT / KC12;   // 8

    extern __shared__ __align__(16) char smc[];
    const uint32_t sbase  = smem_u32(smc);
    const uint32_t bBase  = sbase + 2 * A1B;
    const uint32_t a2Base = sbase + A2OFF;
    char* a2c = smc + A2OFF;

    const int tid  = threadIdx.x;
    const int wid  = tid >> 5;
    const int lane = tid & 31;
    const int rowBlk = blockIdx.x * TM12;

    const __half* W1h = &g_Wth[0][0][0];
    const __half* W2h = &g_Wth[1][0][0];

    float4 vpipe[2];
    auto ldgA1 = [&](int kc) {
#pragma unroll
        for (int i = 0; i < 2; i++) {
            int s  = tid + i * 256;
            int r  = s >> 3;
            int c4 = (s & 7) * 4;
            vpipe[i] = __ldcs((const float4*)(support + (size_t)(rowBlk + r) * CIN + kc + c4));
        }
    };
    auto stsA1 = [&](int buf) {
        char* ab = smc + buf * A1B;
#pragma unroll
        for (int i = 0; i < 2; i++) {
            int s  = tid + i * 256;
            int r  = s >> 3;
            int c4 = (s & 7) * 4;
            uint32_t h[2];
            round4h(vpipe[i], h);
            *(uint2*)(ab + (r * AST12 + c4) * 2) = make_uint2(h[0], h[1]);
        }
    };
    auto cpB = [&](const __half* Wsrc, int kc, int buf) {
        uint32_t bh = bBase + buf * B12B;
#pragma unroll
        for (int i = 0; i < 4; i++) {
            int q   = tid + i * 256;
            int n   = q >> 2;
            int seg = q & 3;
            CP_ASYNC16CG(bh + (uint32_t)(n * AST12 * 2 + seg * 16),
                         Wsrc + (size_t)n * CIN + kc + seg * 8);
        }
    };

    const int wr = (wid & 1) * 32;
    const int wc = (wid >> 1) * 64;
    const int qlane = lane & 3;

    float acc[2][8][4];
#pragma unroll
    for (int mi = 0; mi < 2; mi++)
#pragma unroll
        for (int j = 0; j < 8; j++)
#pragma unroll
            for (int c = 0; c < 4; c++) acc[mi][j][c] = 0.f;

    const int a_r  = (lane & 15);
    const int a_kh = (lane >> 4) * 8;
    const int b_r  = ((lane >> 4) & 1) * 8 + (lane & 7);
    const int b_kh = ((lane >> 3) & 1) * 8;

    // ================= GEMM 1 (K=512, 16 chunks of 32) =================
    ldgA1(0);
    cpB(W1h, 0, 0);
    CP_COMMIT();
    stsA1(0);

#pragma unroll 1
    for (int c = 0; c < NC1; c++) {
        const int cb = c & 1;
        const bool more = (c + 1 < NC1);
        if (more) ldgA1((c + 1) * KC12);
        CP_WAIT0();
        __syncthreads();
        if (more) { cpB(W1h, (c + 1) * KC12, (c + 1) & 1); CP_COMMIT(); }

        const uint32_t aH = sbase + cb * A1B;
        const uint32_t bH = bBase + cb * B12B;
#pragma unroll
        for (int ks = 0; ks < 2; ks++) {
            const int k0 = ks * 16;
            uint32_t ah[2][4];
#pragma unroll
            for (int mi = 0; mi < 2; mi++)
                LDSM4(ah[mi], aH + (uint32_t)((wr + mi * 16 + a_r) * AST12 + k0 + a_kh) * 2);
#pragma unroll
            for (int jp = 0; jp < 4; jp++) {
                uint32_t bhr[4];
                LDSM4(bhr, bH + (uint32_t)((wc + jp * 16 + b_r) * AST12 + k0 + b_kh) * 2);
#pragma unroll
                for (int mi = 0; mi < 2; mi++)
#pragma unroll
                    for (int jj = 0; jj < 2; jj++)
                        MMA_F16(acc[mi][jp * 2 + jj], ah[mi],
                                bhr[jj * 2], bhr[jj * 2 + 1]);
            }
        }
        if (more) stsA1((c + 1) & 1);
    }

    cpB(W2h, 0, 0);
    CP_COMMIT();

    // ---- epilogue 1: GN -> fp16 h1 tile into A2 (8 chunks of 64x32) ----
#pragma unroll
    for (int j = 0; j < 8; j++) {
        const int col = wc + j * 8 + 2 * qlane;
        const int ch  = (wid >> 1) * 2 + (j >> 2);
        const int kk  = (j & 3) * 8 + 2 * qlane;
        const float2 bb = *reinterpret_cast<const float2*>(b1 + col);
        const float2 gg = *reinterpret_cast<const float2*>(g1 + col);
        const float2 be = *reinterpret_cast<const float2*>(be1 + col);
#pragma unroll
        for (int mi = 0; mi < 2; mi++) {
            float y0, y1, y2, y3;
            gn8(acc[mi][j][0] + bb.x, acc[mi][j][1] + bb.y,
                acc[mi][j][2] + bb.x, acc[mi][j][3] + bb.y, gg, be,
                y0, y1, y2, y3);
            const int row0 = wr + mi * 16 + (lane >> 2);
            *(__half2*)(a2c + ch * A1B + (row0 * AST12 + kk) * 2)       = __floats2half2_rn(y0, y1);
            *(__half2*)(a2c + ch * A1B + ((row0 + 8) * AST12 + kk) * 2) = __floats2half2_rn(y2, y3);
        }
    }

#pragma unroll
    for (int mi = 0; mi < 2; mi++)
#pragma unroll
        for (int j = 0; j < 8; j++)
#pragma unroll
            for (int c = 0; c < 4; c++) acc[mi][j][c] = 0.f;

    __syncthreads();

    // ================= GEMM 2 (K=256, 8 chunks, A resident) =================
#pragma unroll 1
    for (int c = 0; c < NC2; c++) {
        const int cb = c & 1;
        const bool more = (c + 1 < NC2);
        CP_WAIT0();
        __syncthreads();
        if (more) { cpB(W2h, (c + 1) * KC12, (c + 1) & 1); CP_COMMIT(); }

        const uint32_t aH = a2Base + c * A1B;
        const uint32_t bH = bBase + cb * B12B;
#pragma unroll
        for (int ks = 0; ks < 2; ks++) {
            const int k0 = ks * 16;
            uint32_t ah[2][4];
#pragma unroll
            for (int mi = 0; mi < 2; mi++)
                LDSM4(ah[mi], aH + (uint32_t)((wr + mi * 16 + a_r) * AST12 + k0 + a_kh) * 2);
#pragma unroll
            for (int jp = 0; jp < 4; jp++) {
                uint32_t bhr[4];
                LDSM4(bhr, bH + (uint32_t)((wc + jp * 16 + b_r) * AST12 + k0 + b_kh) * 2);
#pragma unroll
                for (int mi = 0; mi < 2; mi++)
#pragma unroll
                    for (int jj = 0; jj < 2; jj++)
                        MMA_F16(acc[mi][jp * 2 + jj], ah[mi],
                                bhr[jj * 2], bhr[jj * 2 + 1]);
            }
        }
    }

    // ---- epilogue 2: GN -> fp16 h2 to global (keep in L2 for gather) ----
#pragma unroll
    for (int j = 0; j < 8; j++) {
        const int col = wc + j * 8 + 2 * qlane;
        const float2 bb = *reinterpret_cast<const float2*>(b2 + col);
        const float2 gg = *reinterpret_cast<const float2*>(g2 + col);
        const float2 be = *reinterpret_cast<const float2*>(be2 + col);
#pragma unroll
        for (int mi = 0; mi < 2; mi++) {
            float y0, y1, y2, y3;
            gn8(acc[mi][j][0] + bb.x, acc[mi][j][1] + bb.y,
                acc[mi][j][2] + bb.x, acc[mi][j][3] + bb.y, gg, be,
                y0, y1, y2, y3);
            const size_t row = (size_t)rowBlk + wr + mi * 16 + (lane >> 2);
            *(__half2*)(g_h2f + row * COUT + col)       = __floats2half2_rn(y0, y1);
            *(__half2*)(g_h2f + (row + 8) * COUT + col) = __floats2half2_rn(y2, y3);
        }
    }
}

// ---------------- layer 3: TILE_M3=64, 256 thr, 2 CTAs/SM -----------------
__global__ void __launch_bounds__(256, 2)
layer3_kernel(const float* __restrict__ query,
              const float* __restrict__ b3, const float* __restrict__ g3,
              const float* __restrict__ be3,
              const int*   __restrict__ idx,
              float*       __restrict__ out)
{
    constexpr int NC = COUT / KC3;   // 4

    extern __shared__ __align__(16) char smc[];
    __shared__ int s_grow[TILE_M3];

    const uint32_t sbase = smem_u32(smc);
    const int tid  = threadIdx.x;
    const int wid  = tid >> 5;
    const int lane = tid & 31;
    const int rowBlk = blockIdx.x * TILE_M3;

    const __half* W3h = &g_Wth[2][0][0];

    if (tid < TILE_M3) {
        int grow = rowBlk + tid;
        s_grow[tid] = (grow >> 16) * Mm + idx[grow];
    }
    __syncthreads();

    float4 vpipe[4];
    auto ldgA = [&](int kc) {
#pragma unroll
        for (int i = 0; i < 4; i++) {
            int s  = tid + i * 256;
            int r  = s >> 4;
            int c4 = (s & 15) * 4;
            float4 q = __ldcs((const float4*)(query + (size_t)(rowBlk + r) * COUT + kc + c4));
            uint2 gv = *(const uint2*)(g_h2f + (size_t)s_grow[r] * COUT + kc + c4);
            float2 ga = __half22float2(*reinterpret_cast<__half2*>(&gv.x));
            float2 gb = __half22float2(*reinterpret_cast<__half2*>(&gv.y));
            vpipe[i] = make_float4(q.x + ga.x, q.y + ga.y, q.z + gb.x, q.w + gb.y);
        }
    };
    auto stsA = [&](int buf) {
        char* ab = smc + buf * BUF3;
#pragma unroll
        for (int i = 0; i < 4; i++) {
            int s  = tid + i * 256;
            int r  = s >> 4;
            int c4 = (s & 15) * 4;
            uint32_t h[2];
            round4h(vpipe[i], h);
            *(uint2*)(ab + (r * ASTRE + c4) * 2) = make_uint2(h[0], h[1]);
        }
    };
    auto cpB = [&](int kc, int buf) {
        uint32_t bh = sbase + buf * BUF3 + A3_BYTES;
#pragma unroll
        for (int i = 0; i < 8; i++) {
            int q   = tid + i * 256;
            int n   = q >> 3;
            int seg = q & 7;
            CP_ASYNC16CG(bh + (uint32_t)(n * ASTRE * 2 + seg * 16),
                         W3h + (size_t)n * CIN + kc + seg * 8);
        }
    };

    const int wr = (wid & 1) * 32;
    const int wc = (wid >> 1) * 64;
    const int qlane = lane & 3;

    float acc[2][8][4];
#pragma unroll
    for (int mi = 0; mi < 2; mi++)
#pragma unroll
        for (int j = 0; j < 8; j++)
#pragma unroll
            for (int c = 0; c < 4; c++) acc[mi][j][c] = 0.f;

    const int a_r  = (lane & 15);
    const int a_kh = (lane >> 4) * 8;
    const int b_r  = ((lane >> 4) & 1) * 8 + (lane & 7);
    const int b_kh = ((lane >> 3) & 1) * 8;

    ldgA(0);
    cpB(0, 0);
    CP_COMMIT();
    stsA(0);

#pragma unroll 1
    for (int c = 0; c < NC; c++) {
        const int cb = c & 1;
        const bool more = (c + 1 < NC);
        if (more) ldgA((c + 1) * KC3);
        CP_WAIT0();
        __syncthreads();
        if (more) { cpB((c + 1) * KC3, (c + 1) & 1); CP_COMMIT(); }

        const uint32_t aH = sbase + cb * BUF3;
        const uint32_t bH = aH + A3_BYTES;
#pragma unroll
        for (int ks = 0; ks < 4; ks++) {
            const int k0 = ks * 16;
            uint32_t ah[2][4];
#pragma unroll
            for (int mi = 0; mi < 2; mi++)
                LDSM4(ah[mi], aH + (uint32_t)((wr + mi * 16 + a_r) * ASTRE + k0 + a_kh) * 2);
#pragma unroll
            for (int jp = 0; jp < 4; jp++) {
                uint32_t bhr[4];
                LDSM4(bhr, bH + (uint32_t)((wc + jp * 16 + b_r) * ASTRE + k0 + b_kh) * 2);
#pragma unroll
                for (int mi = 0; mi < 2; mi++)
#pragma unroll
                    for (int jj = 0; jj < 2; jj++)
                        MMA_F16(acc[mi][jp * 2 + jj], ah[mi],
                                bhr[jj * 2], bhr[jj * 2 + 1]);
            }
        }
        if (more) stsA((c + 1) & 1);
    }

    // ---- epilogue: GN -> fp32 out (streaming stores) ----
#pragma unroll
    for (int j = 0; j < 8; j++) {
        const int col = wc + j * 8 + 2 * qlane;
        const float2 bb = *reinterpret_cast<const float2*>(b3 + col);
        const float2 gg = *reinterpret_cast<const float2*>(g3 + col);
        const float2 be = *reinterpret_cast<const float2*>(be3 + col);
#pragma unroll
        for (int mi = 0; mi < 2; mi++) {
            float y0, y1, y2, y3;
            gn8(acc[mi][j][0] + bb.x, acc[mi][j][1] + bb.y,
                acc[mi][j][2] + bb.x, acc[mi][j][3] + bb.y, gg, be,
                y0, y1, y2, y3);
            const size_t row = (size_t)rowBlk + wr + mi * 16 + (lane >> 2);
            __stcs(reinterpret_cast<float2*>(out + row * COUT + col),
                   make_float2(y0, y1));
            __stcs(reinterpret_cast<float2*>(out + (row + 8) * COUT + col),
                   make_float2(y2, y3));
        }
    }
}

extern "C" void kernel_launch(void* const* d_in, const int* in_sizes, int n_in,
                              void* d_out, int out_size)
{
    (void)in_sizes; (void)n_in; (void)out_size;
    const float* query   = (const float*)d_in[0];
    const float* support = (const float*)d_in[1];
    const int*   idx     = (const int*)d_in[2];
    const float* W1  = (const float*)d_in[3];
    const float* b1  = (const float*)d_in[4];
    const float* g1  = (const float*)d_in[5];
    const float* be1 = (const float*)d_in[6];
    const float* W2  = (const float*)d_in[7];
    const float* b2  = (const float*)d_in[8];
    const float* g2  = (const float*)d_in[9];
    const float* be2 = (const float*)d_in[10];
    const float* W3  = (const float*)d_in[11];
    const float* b3  = (const float*)d_in[12];
    const float* g3  = (const float*)d_in[13];
    const float* be3 = (const float*)d_in[14];
    float* out = (float*)d_out;

    split_w_all<<<256, 256>>>(W1, W2, W3);

    cudaFuncSetAttribute(fused12_kernel,
        cudaFuncAttributeMaxDynamicSharedMemorySize, (int)SMEM_F);
    cudaFuncSetAttribute(layer3_kernel,
        cudaFuncAttributeMaxDynamicSharedMemorySize, (int)SMEM_3);

    fused12_kernel<<<ROWS12 / TM12, 256, SMEM_F>>>(
        support, b1, g1, be1, b2, g2, be2);
    layer3_kernel<<<ROWS3 / TILE_M3, 256, SMEM_3>>>(
        query, b3, g3, be3, idx, out);
}